// round 9
// baseline (speedup 1.0000x reference)
#include <cuda_runtime.h>
#include <cuda_bf16.h>
#include <cstdint>
#include <math.h>

#define L_LAYERS 16
#define QD 2048
#define BATCH 4096
#define NMAT 17  // 16 layers + measurement basis

#if defined(__CUDA_ARCH_FEAT_SM103_ALL) || defined(__CUDA_ARCH_FEAT_SM100_ALL) || \
    (defined(__CUDA_ARCH_SPECIFIC__) && (__CUDA_ARCH_SPECIFIC__ >= 1000))
#define HAS_TCGEN05 1
#else
#define HAS_TCGEN05 0
#endif

// ---------------------------------------------------------------------------
// Device scratch. Operands in K-staged, SW64-pre-swizzled layout:
//   [K/32 stages][rows][32 bf16]  -> per-stage CTA tile is contiguous, fetched
// with one cp.async.bulk, landing exactly in SW64 layout for the MMA.
// ---------------------------------------------------------------------------
#define KSTAGES (QD / 32)  // 64
__device__ __nv_bfloat16 g_Wst_hi[(size_t)NMAT * KSTAGES * QD * 32];
__device__ __nv_bfloat16 g_Wst_lo[(size_t)NMAT * KSTAGES * QD * 32];
__device__ __nv_bfloat16 g_Ast_hi[2][(size_t)KSTAGES * BATCH * 32];
__device__ __nv_bfloat16 g_Ast_lo[2][(size_t)KSTAGES * BATCH * 32];
__device__ float g_scales[L_LAYERS][QD];
// per (layer, M-group, N-cta, chunk) arrival counters (8 epilogue warps each)
__device__ int g_flags[NMAT][16][8][8];
// per (matrix, N-cta) weight-conversion counters (16 mi-CTAs each)
__device__ int g_wflags[NMAT][8];

// ---------------------------------------------------------------------------
// PTX helpers
// ---------------------------------------------------------------------------
__device__ __forceinline__ uint32_t smem_u32(const void* p) {
    uint32_t a;
    asm("{ .reg .u64 t; cvta.to.shared.u64 t, %1; cvt.u32.u64 %0, t; }"
        : "=r"(a) : "l"(p));
    return a;
}

__device__ __forceinline__ uint32_t elect_one_pred() {
    uint32_t pred;
    asm volatile(
        "{\n\t.reg .pred p;\n\telect.sync _|p, 0xFFFFFFFF;\n\t"
        "selp.b32 %0, 1, 0, p;\n\t}"
        : "=r"(pred));
    return pred;
}

#define MBARRIER_INIT(addr, count) \
    asm volatile("mbarrier.init.shared.b64 [%0], %1;" \
                 :: "r"((uint32_t)(addr)), "r"((uint32_t)(count)) : "memory")

#define MBARRIER_EXPECT_TX(addr, tx) \
    asm volatile("mbarrier.arrive.expect_tx.shared.b64 _, [%0], %1;" \
                 :: "r"((uint32_t)(addr)), "r"((uint32_t)(tx)) : "memory")

#define MBARRIER_WAIT_PARITY(mbar_smem_addr, phase_parity) do { \
    uint32_t _mbar = (uint32_t)(mbar_smem_addr); \
    uint32_t _parity = (uint32_t)(phase_parity); \
    uint32_t _done; \
    asm volatile( \
        "{\n\t.reg .pred p;\n\t" \
        "mbarrier.try_wait.parity.acquire.cta.shared::cta.b64 p, [%1], %2;\n\t" \
        "selp.b32 %0, 1, 0, p;\n\t}" \
        : "=r"(_done) : "r"(_mbar), "r"(_parity) : "memory"); \
    if (!_done) { \
        asm volatile( \
            "{\n\t.reg .pred P1;\n\t" \
            "WAIT_LOOP_%=:\n\t" \
            "mbarrier.try_wait.parity.acquire.cta.shared::cta.b64 P1, [%0], %1, 0x989680;\n\t" \
            "@P1 bra.uni WAIT_DONE_%=;\n\t" \
            "bra.uni WAIT_LOOP_%=;\n\t" \
            "WAIT_DONE_%=:\n\t}" \
            :: "r"(_mbar), "r"(_parity) : "memory"); \
    } \
} while (0)

__device__ __forceinline__ void bulk_cp(uint32_t dst, const void* src,
                                        uint32_t bytes, uint32_t mbar) {
    asm volatile(
        "cp.async.bulk.shared::cta.global.mbarrier::complete_tx::bytes "
        "[%0], [%1], %2, [%3];"
        :: "r"(dst), "l"(src), "r"(bytes), "r"(mbar) : "memory");
}

#if HAS_TCGEN05
#define TCGEN05_ALLOC(smem_result_addr, nCols) \
    asm volatile("tcgen05.alloc.cta_group::1.sync.aligned.shared::cta.b32 [%0], %1;" \
                 :: "r"((uint32_t)(smem_result_addr)), "r"((uint32_t)(nCols)) : "memory")
#define TCGEN05_DEALLOC(tmem_addr, nCols) \
    asm volatile("tcgen05.dealloc.cta_group::1.sync.aligned.b32 %0, %1;" \
                 :: "r"(tmem_addr), "r"((uint32_t)(nCols)))
#define TCGEN05_RELINQUISH() \
    asm volatile("tcgen05.relinquish_alloc_permit.cta_group::1.sync.aligned;")
#define TCGEN05_COMMIT(mbar) \
    asm volatile("tcgen05.commit.cta_group::1.mbarrier::arrive::one.shared::cluster.b64 [%0];" \
                 :: "r"((uint32_t)(mbar)) : "memory")
#define TCGEN05_FENCE_AFTER() \
    asm volatile("tcgen05.fence::after_thread_sync;" ::: "memory")
#define TCGEN05_FENCE_BEFORE() \
    asm volatile("tcgen05.fence::before_thread_sync;" ::: "memory")
#define TCGEN05_WAIT_LD() \
    asm volatile("tcgen05.wait::ld.sync.aligned;" ::: "memory")

#define TCGEN05_LD_32X32B_X32(r, tmem_addr) \
    asm volatile( \
        "tcgen05.ld.sync.aligned.32x32b.x32.b32 " \
        "{%0, %1, %2, %3, %4, %5, %6, %7, " \
        " %8, %9, %10, %11, %12, %13, %14, %15, " \
        " %16, %17, %18, %19, %20, %21, %22, %23, " \
        " %24, %25, %26, %27, %28, %29, %30, %31}, [%32];" \
        : "=r"((r)[0]),  "=r"((r)[1]),  "=r"((r)[2]),  "=r"((r)[3]), \
          "=r"((r)[4]),  "=r"((r)[5]),  "=r"((r)[6]),  "=r"((r)[7]), \
          "=r"((r)[8]),  "=r"((r)[9]),  "=r"((r)[10]), "=r"((r)[11]), \
          "=r"((r)[12]), "=r"((r)[13]), "=r"((r)[14]), "=r"((r)[15]), \
          "=r"((r)[16]), "=r"((r)[17]), "=r"((r)[18]), "=r"((r)[19]), \
          "=r"((r)[20]), "=r"((r)[21]), "=r"((r)[22]), "=r"((r)[23]), \
          "=r"((r)[24]), "=r"((r)[25]), "=r"((r)[26]), "=r"((r)[27]), \
          "=r"((r)[28]), "=r"((r)[29]), "=r"((r)[30]), "=r"((r)[31]) \
        : "r"(tmem_addr))

__device__ __forceinline__ void mma_f16_ss(uint32_t d, uint64_t da, uint64_t db,
                                           uint32_t idesc, uint32_t en) {
    asm volatile(
        "{\n\t.reg .pred p;\n\tsetp.ne.u32 p, %4, 0;\n\t"
        "tcgen05.mma.cta_group::1.kind::f16 [%0], %1, %2, %3, {%5,%5,%5,%5}, p;\n\t}"
        :: "r"(d), "l"(da), "l"(db), "r"(idesc), "r"(en), "r"(0u) : "memory");
}
#endif  // HAS_TCGEN05

// SW64 smem matrix descriptor: layout=4 (SW64), version=1, SBO=32, LBO=1.
static constexpr uint64_t DESC_SW64_BASE =
    (uint64_t(4) << 61) | (uint64_t(1) << 46) | (uint64_t(32) << 32) | (uint64_t(1) << 16);
#define MAKE_DESC64(a) (DESC_SW64_BASE | ((uint64_t)((a) >> 4) & 0x3FFF))

// ---------------------------------------------------------------------------
// Prep kernels (staged layout, SW64 swizzle pre-applied: unit u ^= (row>>1)&3)
// ---------------------------------------------------------------------------
__global__ void prep_small_kernel(const float* __restrict__ angles) {
    int idx = blockIdx.x * blockDim.x + threadIdx.x;
    if (idx < NMAT * 16 * 8 * 8) ((int*)g_flags)[idx] = 0;
    if (idx < NMAT * 8) ((int*)g_wflags)[idx] = 0;
    if (idx < L_LAYERS * QD) {
        const float* a = angles + idx * 3;
        (&g_scales[0][0])[idx] = cosf(0.5f * a[0]) * cosf(0.5f * a[1]) * cosf(0.5f * a[2]);
    }
}

// Pre-convert only matrices 0..1; the rest are converted inside the
// persistent kernel, overlapped with GEMM compute.
__global__ void convert_weights_staged(const float* __restrict__ weights,
                                       const float* __restrict__ meas) {
    __shared__ __nv_bfloat16 sh[8][1024];
    __shared__ __nv_bfloat16 sl[8][1024];
    const int m = blockIdx.z;
    const float* src = (m < L_LAYERS) ? (weights + (size_t)m * QD * QD) : meas;
    const int sK = blockIdx.x;
    const int w = threadIdx.x >> 5, ln = threadIdx.x & 31;
    const int n0 = (blockIdx.y * 8 + w) * 32;
    const int uperm = (ln >> 1) & 3;
#pragma unroll 8
    for (int j = 0; j < 32; ++j) {
        float x = src[(size_t)(sK * 32 + j) * QD + n0 + ln];
        __nv_bfloat16 h = __float2bfloat16(x);
        __nv_bfloat16 l = __float2bfloat16(x - __bfloat162float(h));
        int u = j >> 3, e = j & 7;
        int pos = ln * 32 + ((u ^ uperm) << 3) + e;
        sh[w][pos] = h;
        sl[w][pos] = l;
    }
    __syncwarp();
    size_t rowbase = ((size_t)m * KSTAGES + sK) * QD + n0;
    uint4* dh = (uint4*)(g_Wst_hi + rowbase * 32);
    uint4* dl = (uint4*)(g_Wst_lo + rowbase * 32);
    const uint4* s4h = (const uint4*)sh[w];
    const uint4* s4l = (const uint4*)sl[w];
#pragma unroll
    for (int p = 0; p < 4; ++p) {
        dh[ln + 32 * p] = s4h[ln + 32 * p];
        dl[ln + 32 * p] = s4l[ln + 32 * p];
    }
}

__global__ void convert_input_staged(const float* __restrict__ in) {
    __shared__ __nv_bfloat16 sh[8][1024];
    __shared__ __nv_bfloat16 sl[8][1024];
    const int sK = blockIdx.x;
    const int w = threadIdx.x >> 5, ln = threadIdx.x & 31;
    const int r0 = (blockIdx.y * 8 + w) * 32;
    const float sc = g_scales[0][sK * 32 + ln];
    const int u = ln >> 3, e = ln & 7;
#pragma unroll 8
    for (int j = 0; j < 32; ++j) {
        float x = in[(size_t)(r0 + j) * QD + sK * 32 + ln] * sc;
        __nv_bfloat16 h = __float2bfloat16(x);
        __nv_bfloat16 l = __float2bfloat16(x - __bfloat162float(h));
        int pos = j * 32 + ((u ^ ((j >> 1) & 3)) << 3) + e;
        sh[w][pos] = h;
        sl[w][pos] = l;
    }
    __syncwarp();
    size_t rowbase = (size_t)sK * BATCH + r0;
    uint4* dh = (uint4*)(g_Ast_hi[0] + rowbase * 32);
    uint4* dl = (uint4*)(g_Ast_lo[0] + rowbase * 32);
    const uint4* s4h = (const uint4*)sh[w];
    const uint4* s4l = (const uint4*)sl[w];
#pragma unroll
    for (int p = 0; p < 4; ++p) {
        dh[ln + 32 * p] = s4h[ln + 32 * p];
        dl[ln + 32 * p] = s4l[ln + 32 * p];
    }
}

// ---------------------------------------------------------------------------
// Persistent 17-layer chained GEMM. Grid (8,16) = 128 CTAs = one wave.
// - K-rotation: CTA (mi,ni) walks stages k=(j+ni*8)&63, so its first consumed
//   A-chunks at a layer boundary are the ones ITSELF just produced.
// - Weight conversion for matrix l+2 runs on the epilogue warps during layer
//   l's mainloop (overlapped with MMA); matrices 0..1 pre-converted.
// Warps 0-7: epilogue + W-convert. Warp 8: bulk producer. Warp 9: MMA.
// ---------------------------------------------------------------------------
#define BM 256
#define BN 256
#define NSTAGE 3
#define TILE_B 16384
#define STAGE_B (4 * TILE_B)  // 64KB
#define K_ITERS KSTAGES       // 64
#define EPI_SMEM 32768        // 8 warps x 4KB staging
#define MMA_IDESC 0x8400490u  // F32 acc, BF16 a/b, M=128, N=256

__global__ __launch_bounds__(320, 1)
void qgemm_persistent(float* __restrict__ outF,
                      const float* __restrict__ weights,
                      const float* __restrict__ meas) {
#if HAS_TCGEN05
    extern __shared__ __align__(1024) char smem_dyn[];
    __shared__ __align__(8) unsigned long long s_bars[7];
    __shared__ uint32_t s_tmem;

    const int tid = threadIdx.x;
    const int wid = tid >> 5;
    const int lid = tid & 31;

    const uint32_t raw = smem_u32(smem_dyn);
    const uint32_t smem_base = (raw + 1023u) & ~1023u;
    char* smem_g = smem_dyn + (smem_base - raw);

    uint32_t bar_full[3], bar_empty[3], bar_done;
#pragma unroll
    for (int i = 0; i < 3; ++i) {
        bar_full[i]  = smem_u32(&s_bars[i]);
        bar_empty[i] = smem_u32(&s_bars[3 + i]);
    }
    bar_done = smem_u32(&s_bars[6]);

    if (tid == 0) {
#pragma unroll
        for (int i = 0; i < 3; ++i) {
            MBARRIER_INIT(bar_full[i], 1);
            MBARRIER_INIT(bar_empty[i], 1);
        }
        MBARRIER_INIT(bar_done, 1);
    }
    if (wid == 8) TCGEN05_ALLOC(smem_u32(&s_tmem), 512);
    __syncthreads();
    const uint32_t tmem_d = s_tmem;

    const int mi = blockIdx.y;
    const int ni = blockIdx.x;
    const int blockN = ni * BN;
    const int blockM = mi * BM;
    const int rot = ni * 8;
    const size_t MATB = (size_t)KSTAGES * QD * 64;

    if (wid == 8) {
        // ---- producer warp (rotated stage order) ------------------------
        int s = 0, w = 0;
        for (int l = 0; l < NMAT; ++l) {
            // wait for this layer's weights to be converted (always ready in
            // steady state: converted two layers ago)
            if (l >= 2) {
                const int* wf = &g_wflags[l][ni];
                int v;
                do {
                    asm volatile("ld.acquire.gpu.global.b32 %0, [%1];"
                                 : "=r"(v) : "l"(wf) : "memory");
                } while (v < 16);
                asm volatile("fence.proxy.async;" ::: "memory");
            }
            unsigned long long ready = (l == 0) ? ~0ull : 0ull;
            for (int j = 0; j < K_ITERS; ++j) {
                const int k = (j + rot) & 63;
                if (l * K_ITERS + j >= NSTAGE)
                    MBARRIER_WAIT_PARITY(bar_empty[s], (w + 1) & 1);
                const uint32_t stage = smem_base + s * STAGE_B;
                const uint32_t ep = elect_one_pred();
                if (ep) MBARRIER_EXPECT_TX(bar_full[s], STAGE_B);
                const size_t boff = (size_t)l * MATB + ((size_t)k * QD + blockN) * 64;
                if (ep) {
                    bulk_cp(stage + 2 * TILE_B, (const char*)g_Wst_hi + boff, TILE_B, bar_full[s]);
                    bulk_cp(stage + 3 * TILE_B, (const char*)g_Wst_lo + boff, TILE_B, bar_full[s]);
                }
                // A: warp-cooperative poll of prev-layer chunk flags (j-space)
                while (!((ready >> j) & 1)) {
                    int idx = j + lid;
                    int v = 0;
                    if (idx < K_ITERS) {
                        const int ki = (idx + rot) & 63;
                        const int* f = &g_flags[l - 1][mi][ki >> 3][ki & 7];
                        asm volatile("ld.acquire.gpu.global.b32 %0, [%1];"
                                     : "=r"(v) : "l"(f) : "memory");
                    }
                    unsigned b = __ballot_sync(0xFFFFFFFFu, v >= 8);
                    ready |= ((unsigned long long)b) << j;
                }
                if (ep) {
                    asm volatile("fence.proxy.async;" ::: "memory");
                    const int pb = l & 1;
                    const size_t aoff = ((size_t)k * BATCH + blockM) * 64;
                    bulk_cp(stage,          (const char*)g_Ast_hi[pb] + aoff, TILE_B, bar_full[s]);
                    bulk_cp(stage + TILE_B, (const char*)g_Ast_lo[pb] + aoff, TILE_B, bar_full[s]);
                }
                if (++s == NSTAGE) { s = 0; ++w; }
            }
        }
    } else if (wid == 9) {
        // ---- MMA warp ---------------------------------------------------
        int s = 0, w = 0;
        for (int l = 0; l < NMAT; ++l) {
            asm volatile("bar.sync 1, 288;" ::: "memory");  // TMEM free handoff
            TCGEN05_FENCE_AFTER();
            for (int j = 0; j < K_ITERS; ++j) {
                MBARRIER_WAIT_PARITY(bar_full[s], w & 1);
                const uint32_t stage = smem_base + s * STAGE_B;
                if (elect_one_pred()) {
                    const uint64_t dBh = MAKE_DESC64(stage + 2 * TILE_B);
                    const uint64_t dBl = MAKE_DESC64(stage + 3 * TILE_B);
#pragma unroll
                    for (int h = 0; h < 2; ++h) {
                        const uint64_t dAh = MAKE_DESC64(stage + h * 8192);
                        const uint64_t dAl = MAKE_DESC64(stage + TILE_B + h * 8192);
                        const uint32_t d = tmem_d + h * 256;
#pragma unroll
                        for (int c = 0; c < 2; ++c) {
                            uint32_t en0 = (j == 0 && c == 0) ? 0u : 1u;
                            mma_f16_ss(d, dAh + 2 * c, dBh + 2 * c, MMA_IDESC, en0);
                            mma_f16_ss(d, dAh + 2 * c, dBl + 2 * c, MMA_IDESC, 1);
                            mma_f16_ss(d, dAl + 2 * c, dBh + 2 * c, MMA_IDESC, 1);
                        }
                    }
                    TCGEN05_COMMIT(bar_empty[s]);
                }
                if (++s == NSTAGE) { s = 0; ++w; }
            }
            if (elect_one_pred()) TCGEN05_COMMIT(bar_done);
        }
    } else {
        // ---- epilogue warps 0-7 (+ overlapped W conversion) ------------
        const int half = wid >> 2;
        const int rbase = blockM + half * 128 + (wid & 3) * 32;
        const int row = rbase + lid;
        const int uperm = (lid >> 1) & 3;
        char* wsm = smem_g + NSTAGE * STAGE_B + wid * 4096;  // 2KB hi + 2KB lo
        for (int l = 0; l < NMAT; ++l) {
            // Convert weight matrix l+2 (runs concurrent with layer l MMA).
            if (l + 2 < NMAT) {
                const int m = l + 2;
                const float* src = (m < L_LAYERS) ? (weights + (size_t)m * QD * QD) : meas;
                const int sK = mi * 4 + (wid >> 1);   // stage handled by this warp
                const int rh = wid & 1;               // row half of the 256-slice
#pragma unroll 1
                for (int g = 0; g < 4; ++g) {
                    const int n0g = ni * 256 + rh * 128 + g * 32;
#pragma unroll 8
                    for (int jj = 0; jj < 32; ++jj) {
                        float x = src[(size_t)(sK * 32 + jj) * QD + n0g + lid];
                        __nv_bfloat16 hbf = __float2bfloat16(x);
                        __nv_bfloat16 lbf = __float2bfloat16(x - __bfloat162float(hbf));
                        int u = jj >> 3, e = jj & 7;
                        int pos = lid * 32 + ((u ^ uperm) << 3) + e;
                        ((__nv_bfloat16*)wsm)[pos] = hbf;
                        ((__nv_bfloat16*)(wsm + 2048))[pos] = lbf;
                    }
                    __syncwarp();
                    size_t rowbase = ((size_t)m * KSTAGES + sK) * QD + n0g;
                    uint4* dh = (uint4*)(g_Wst_hi + rowbase * 32);
                    uint4* dl = (uint4*)(g_Wst_lo + rowbase * 32);
                    const uint4* s4h = (const uint4*)wsm;
                    const uint4* s4l = (const uint4*)(wsm + 2048);
#pragma unroll
                    for (int p = 0; p < 4; ++p) {
                        dh[lid + 32 * p] = s4h[lid + 32 * p];
                        dl[lid + 32 * p] = s4l[lid + 32 * p];
                    }
                    __syncwarp();
                }
                asm volatile("bar.sync 3, 256;" ::: "memory");  // all 8 warps done
                if (wid == 0 && lid == 0) {
                    asm volatile("red.release.gpu.global.add.s32 [%0], 1;"
                                 :: "l"(&g_wflags[m][ni]) : "memory");
                }
            }
            // Drain this layer's accumulators.
            asm volatile("bar.sync 1, 288;" ::: "memory");
            MBARRIER_WAIT_PARITY(bar_done, l & 1);
            TCGEN05_FENCE_AFTER();
            const float* scaleNext = (l < L_LAYERS - 1) ? g_scales[l + 1] : nullptr;
            const int fpout = (l == NMAT - 1);
            const int wb = (l + 1) & 1;
            __nv_bfloat16* outHi = g_Ast_hi[wb];
            __nv_bfloat16* outLo = g_Ast_lo[wb];
#pragma unroll 1
            for (int ch = 0; ch < 8; ++ch) {
                uint32_t regs[32];
                TCGEN05_LD_32X32B_X32(regs, tmem_d + half * 256 + ch * 32);
                TCGEN05_WAIT_LD();
                const int c0 = blockN + ch * 32;
                if (fpout) {
                    float* dst = outF + (size_t)row * QD + c0;
#pragma unroll
                    for (int g = 0; g < 8; ++g)
                        *(float4*)(dst + g * 4) = make_float4(
                            __uint_as_float(regs[g * 4 + 0]), __uint_as_float(regs[g * 4 + 1]),
                            __uint_as_float(regs[g * 4 + 2]), __uint_as_float(regs[g * 4 + 3]));
                } else {
                    uint32_t hp[16], lp[16];
#pragma unroll
                    for (int q = 0; q < 16; ++q) {
                        float v0 = __uint_as_float(regs[2 * q]);
                        float v1 = __uint_as_float(regs[2 * q + 1]);
                        if (scaleNext) {
                            const float2 s2 = *(const float2*)(scaleNext + c0 + 2 * q);
                            v0 *= s2.x;
                            v1 *= s2.y;
                        }
                        uint32_t b0 = __float_as_uint(v0), b1 = __float_as_uint(v1);
                        float lo0 = v0 - __uint_as_float(b0 & 0xFFFF0000u);
                        float lo1 = v1 - __uint_as_float(b1 & 0xFFFF0000u);
                        uint32_t hh;
                        asm("prmt.b32 %0, %1, %2, 0x7632;" : "=r"(hh) : "r"(b0), "r"(b1));
                        hp[q] = hh;
                        uint32_t lpk;
                        asm("cvt.rn.bf16x2.f32 %0, %1, %2;" : "=r"(lpk) : "f"(lo1), "f"(lo0));
                        lp[q] = lpk;
                    }
                    // stage into smem (swizzled), then coalesced 2KB copy-out
#pragma unroll
                    for (int u = 0; u < 4; ++u) {
                        int up = (u ^ uperm) << 4;
                        *(uint4*)(wsm + lid * 64 + up) =
                            make_uint4(hp[4 * u], hp[4 * u + 1], hp[4 * u + 2], hp[4 * u + 3]);
                        *(uint4*)(wsm + 2048 + lid * 64 + up) =
                            make_uint4(lp[4 * u], lp[4 * u + 1], lp[4 * u + 2], lp[4 * u + 3]);
                    }
                    __syncwarp();
                    const int sK2 = c0 >> 5;
                    size_t rowbase = (size_t)sK2 * BATCH + rbase;
                    uint4* dh = (uint4*)(outHi + rowbase * 32);
                    uint4* dl = (uint4*)(outLo + rowbase * 32);
                    const uint4* s4h = (const uint4*)wsm;
                    const uint4* s4l = (const uint4*)(wsm + 2048);
#pragma unroll
                    for (int p = 0; p < 4; ++p) {
                        dh[lid + 32 * p] = s4h[lid + 32 * p];
                        dl[lid + 32 * p] = s4l[lid + 32 * p];
                    }
                    __syncwarp();
                    if (lid == 0) {
                        asm volatile("red.release.gpu.global.add.s32 [%0], 1;"
                                     :: "l"(&g_flags[l][mi][ni][ch]) : "memory");
                    }
                }
            }
            TCGEN05_FENCE_BEFORE();
        }
    }

    __syncthreads();
    if (wid == 8) {
        TCGEN05_RELINQUISH();
        TCGEN05_DEALLOC(tmem_d, 512);
    }
#endif  // HAS_TCGEN05
}

// ---------------------------------------------------------------------------
// Launch
// ---------------------------------------------------------------------------
extern "C" void kernel_launch(void* const* d_in, const int* in_sizes, int n_in,
                              void* d_out, int out_size) {
    const float* input_state = (const float*)d_in[0];
    const float* angles      = (const float*)d_in[1];
    const float* weights     = (const float*)d_in[2];
    const float* meas_basis  = (const float*)d_in[3];
    float* out = (float*)d_out;
    (void)in_sizes; (void)n_in; (void)out_size;

    const size_t dyn = NSTAGE * STAGE_B + EPI_SMEM + 1024;  // 225 KB
    cudaFuncSetAttribute(qgemm_persistent, cudaFuncAttributeMaxDynamicSharedMemorySize, dyn);

    prep_small_kernel<<<128, 256>>>(angles);
    // only matrices 0 and 1 up front; the rest convert inside the GEMM
    convert_weights_staged<<<dim3(KSTAGES, QD / 256, 2), 256>>>(weights, meas_basis);
    convert_input_staged<<<dim3(KSTAGES, BATCH / 256), 256>>>(input_state);

    dim3 grid(QD / BN, BATCH / BM);  // (8, 16) = 128 CTAs, one wave
    qgemm_persistent<<<grid, 320, dyn>>>(out, weights, meas_basis);
}

// round 10
// speedup vs baseline: 1.0872x; 1.0872x over previous
#include <cuda_runtime.h>
#include <cuda_bf16.h>
#include <cstdint>
#include <math.h>

#define L_LAYERS 16
#define QD 2048
#define BATCH 4096
#define NMAT 17  // 16 layers + measurement basis

#if defined(__CUDA_ARCH_FEAT_SM103_ALL) || defined(__CUDA_ARCH_FEAT_SM100_ALL) || \
    (defined(__CUDA_ARCH_SPECIFIC__) && (__CUDA_ARCH_SPECIFIC__ >= 1000))
#define HAS_TCGEN05 1
#else
#define HAS_TCGEN05 0
#endif

// ---------------------------------------------------------------------------
// Device scratch. Operands in K-staged, SW64-pre-swizzled layout:
//   [K/32 stages][rows][32 bf16]  -> per-stage CTA tile is contiguous, fetched
// with one cp.async.bulk, landing exactly in SW64 layout for the MMA.
// ---------------------------------------------------------------------------
#define KSTAGES (QD / 32)  // 64
__device__ __nv_bfloat16 g_Wst_hi[(size_t)NMAT * KSTAGES * QD * 32];
__device__ __nv_bfloat16 g_Wst_lo[(size_t)NMAT * KSTAGES * QD * 32];
__device__ __nv_bfloat16 g_Ast_hi[2][(size_t)KSTAGES * BATCH * 32];
__device__ __nv_bfloat16 g_Ast_lo[2][(size_t)KSTAGES * BATCH * 32];
__device__ float g_scales[L_LAYERS][QD];
// per (layer, M-group, N-cta, chunk) arrival counters (8 epilogue warps each)
__device__ int g_flags[NMAT][16][8][8];
// per (matrix, N-cta) weight-conversion counters (16 mi-CTAs each)
__device__ int g_wflags[NMAT][8];

// ---------------------------------------------------------------------------
// PTX helpers
// ---------------------------------------------------------------------------
__device__ __forceinline__ uint32_t smem_u32(const void* p) {
    uint32_t a;
    asm("{ .reg .u64 t; cvta.to.shared.u64 t, %1; cvt.u32.u64 %0, t; }"
        : "=r"(a) : "l"(p));
    return a;
}

__device__ __forceinline__ uint32_t elect_one_pred() {
    uint32_t pred;
    asm volatile(
        "{\n\t.reg .pred p;\n\telect.sync _|p, 0xFFFFFFFF;\n\t"
        "selp.b32 %0, 1, 0, p;\n\t}"
        : "=r"(pred));
    return pred;
}

#define MBARRIER_INIT(addr, count) \
    asm volatile("mbarrier.init.shared.b64 [%0], %1;" \
                 :: "r"((uint32_t)(addr)), "r"((uint32_t)(count)) : "memory")

#define MBARRIER_EXPECT_TX(addr, tx) \
    asm volatile("mbarrier.arrive.expect_tx.shared.b64 _, [%0], %1;" \
                 :: "r"((uint32_t)(addr)), "r"((uint32_t)(tx)) : "memory")

#define MBARRIER_WAIT_PARITY(mbar_smem_addr, phase_parity) do { \
    uint32_t _mbar = (uint32_t)(mbar_smem_addr); \
    uint32_t _parity = (uint32_t)(phase_parity); \
    uint32_t _done; \
    asm volatile( \
        "{\n\t.reg .pred p;\n\t" \
        "mbarrier.try_wait.parity.acquire.cta.shared::cta.b64 p, [%1], %2;\n\t" \
        "selp.b32 %0, 1, 0, p;\n\t}" \
        : "=r"(_done) : "r"(_mbar), "r"(_parity) : "memory"); \
    if (!_done) { \
        asm volatile( \
            "{\n\t.reg .pred P1;\n\t" \
            "WAIT_LOOP_%=:\n\t" \
            "mbarrier.try_wait.parity.acquire.cta.shared::cta.b64 P1, [%0], %1, 0x989680;\n\t" \
            "@P1 bra.uni WAIT_DONE_%=;\n\t" \
            "bra.uni WAIT_LOOP_%=;\n\t" \
            "WAIT_DONE_%=:\n\t}" \
            :: "r"(_mbar), "r"(_parity) : "memory"); \
    } \
} while (0)

__device__ __forceinline__ void bulk_cp(uint32_t dst, const void* src,
                                        uint32_t bytes, uint32_t mbar) {
    asm volatile(
        "cp.async.bulk.shared::cta.global.mbarrier::complete_tx::bytes "
        "[%0], [%1], %2, [%3];"
        :: "r"(dst), "l"(src), "r"(bytes), "r"(mbar) : "memory");
}

#if HAS_TCGEN05
#define TCGEN05_ALLOC(smem_result_addr, nCols) \
    asm volatile("tcgen05.alloc.cta_group::1.sync.aligned.shared::cta.b32 [%0], %1;" \
                 :: "r"((uint32_t)(smem_result_addr)), "r"((uint32_t)(nCols)) : "memory")
#define TCGEN05_DEALLOC(tmem_addr, nCols) \
    asm volatile("tcgen05.dealloc.cta_group::1.sync.aligned.b32 %0, %1;" \
                 :: "r"(tmem_addr), "r"((uint32_t)(nCols)))
#define TCGEN05_RELINQUISH() \
    asm volatile("tcgen05.relinquish_alloc_permit.cta_group::1.sync.aligned;")
#define TCGEN05_COMMIT(mbar) \
    asm volatile("tcgen05.commit.cta_group::1.mbarrier::arrive::one.shared::cluster.b64 [%0];" \
                 :: "r"((uint32_t)(mbar)) : "memory")
#define TCGEN05_FENCE_AFTER() \
    asm volatile("tcgen05.fence::after_thread_sync;" ::: "memory")
#define TCGEN05_FENCE_BEFORE() \
    asm volatile("tcgen05.fence::before_thread_sync;" ::: "memory")
#define TCGEN05_WAIT_LD() \
    asm volatile("tcgen05.wait::ld.sync.aligned;" ::: "memory")

#define TCGEN05_LD_32X32B_X32(r, tmem_addr) \
    asm volatile( \
        "tcgen05.ld.sync.aligned.32x32b.x32.b32 " \
        "{%0, %1, %2, %3, %4, %5, %6, %7, " \
        " %8, %9, %10, %11, %12, %13, %14, %15, " \
        " %16, %17, %18, %19, %20, %21, %22, %23, " \
        " %24, %25, %26, %27, %28, %29, %30, %31}, [%32];" \
        : "=r"((r)[0]),  "=r"((r)[1]),  "=r"((r)[2]),  "=r"((r)[3]), \
          "=r"((r)[4]),  "=r"((r)[5]),  "=r"((r)[6]),  "=r"((r)[7]), \
          "=r"((r)[8]),  "=r"((r)[9]),  "=r"((r)[10]), "=r"((r)[11]), \
          "=r"((r)[12]), "=r"((r)[13]), "=r"((r)[14]), "=r"((r)[15]), \
          "=r"((r)[16]), "=r"((r)[17]), "=r"((r)[18]), "=r"((r)[19]), \
          "=r"((r)[20]), "=r"((r)[21]), "=r"((r)[22]), "=r"((r)[23]), \
          "=r"((r)[24]), "=r"((r)[25]), "=r"((r)[26]), "=r"((r)[27]), \
          "=r"((r)[28]), "=r"((r)[29]), "=r"((r)[30]), "=r"((r)[31]) \
        : "r"(tmem_addr))

__device__ __forceinline__ void mma_f16_ss(uint32_t d, uint64_t da, uint64_t db,
                                           uint32_t idesc, uint32_t en) {
    asm volatile(
        "{\n\t.reg .pred p;\n\tsetp.ne.u32 p, %4, 0;\n\t"
        "tcgen05.mma.cta_group::1.kind::f16 [%0], %1, %2, %3, {%5,%5,%5,%5}, p;\n\t}"
        :: "r"(d), "l"(da), "l"(db), "r"(idesc), "r"(en), "r"(0u) : "memory");
}
#endif  // HAS_TCGEN05

// SW64 smem matrix descriptor: layout=4 (SW64), version=1, SBO=32, LBO=1.
static constexpr uint64_t DESC_SW64_BASE =
    (uint64_t(4) << 61) | (uint64_t(1) << 46) | (uint64_t(32) << 32) | (uint64_t(1) << 16);
#define MAKE_DESC64(a) (DESC_SW64_BASE | ((uint64_t)((a) >> 4) & 0x3FFF))

// ---------------------------------------------------------------------------
// Prep kernels (staged layout, SW64 swizzle pre-applied: unit u ^= (row>>1)&3)
// ---------------------------------------------------------------------------
__global__ void prep_small_kernel(const float* __restrict__ angles) {
    int idx = blockIdx.x * blockDim.x + threadIdx.x;
    if (idx < NMAT * 16 * 8 * 8) ((int*)g_flags)[idx] = 0;
    if (idx < NMAT * 8) ((int*)g_wflags)[idx] = 0;
    if (idx < L_LAYERS * QD) {
        const float* a = angles + idx * 3;
        (&g_scales[0][0])[idx] = cosf(0.5f * a[0]) * cosf(0.5f * a[1]) * cosf(0.5f * a[2]);
    }
}

// Pre-convert only matrices 0..1; the rest are converted inside the
// persistent kernel, overlapped with GEMM compute.
__global__ void convert_weights_staged(const float* __restrict__ weights,
                                       const float* __restrict__ meas) {
    __shared__ __nv_bfloat16 sh[8][1024];
    __shared__ __nv_bfloat16 sl[8][1024];
    const int m = blockIdx.z;
    const float* src = (m < L_LAYERS) ? (weights + (size_t)m * QD * QD) : meas;
    const int sK = blockIdx.x;
    const int w = threadIdx.x >> 5, ln = threadIdx.x & 31;
    const int n0 = (blockIdx.y * 8 + w) * 32;
    const int uperm = (ln >> 1) & 3;
#pragma unroll 8
    for (int j = 0; j < 32; ++j) {
        float x = src[(size_t)(sK * 32 + j) * QD + n0 + ln];
        __nv_bfloat16 h = __float2bfloat16(x);
        __nv_bfloat16 l = __float2bfloat16(x - __bfloat162float(h));
        int u = j >> 3, e = j & 7;
        int pos = ln * 32 + ((u ^ uperm) << 3) + e;
        sh[w][pos] = h;
        sl[w][pos] = l;
    }
    __syncwarp();
    size_t rowbase = ((size_t)m * KSTAGES + sK) * QD + n0;
    uint4* dh = (uint4*)(g_Wst_hi + rowbase * 32);
    uint4* dl = (uint4*)(g_Wst_lo + rowbase * 32);
    const uint4* s4h = (const uint4*)sh[w];
    const uint4* s4l = (const uint4*)sl[w];
#pragma unroll
    for (int p = 0; p < 4; ++p) {
        dh[ln + 32 * p] = s4h[ln + 32 * p];
        dl[ln + 32 * p] = s4l[ln + 32 * p];
    }
}

__global__ void convert_input_staged(const float* __restrict__ in) {
    __shared__ __nv_bfloat16 sh[8][1024];
    __shared__ __nv_bfloat16 sl[8][1024];
    const int sK = blockIdx.x;
    const int w = threadIdx.x >> 5, ln = threadIdx.x & 31;
    const int r0 = (blockIdx.y * 8 + w) * 32;
    const float sc = g_scales[0][sK * 32 + ln];
    const int u = ln >> 3, e = ln & 7;
#pragma unroll 8
    for (int j = 0; j < 32; ++j) {
        float x = in[(size_t)(r0 + j) * QD + sK * 32 + ln] * sc;
        __nv_bfloat16 h = __float2bfloat16(x);
        __nv_bfloat16 l = __float2bfloat16(x - __bfloat162float(h));
        int pos = j * 32 + ((u ^ ((j >> 1) & 3)) << 3) + e;
        sh[w][pos] = h;
        sl[w][pos] = l;
    }
    __syncwarp();
    size_t rowbase = (size_t)sK * BATCH + r0;
    uint4* dh = (uint4*)(g_Ast_hi[0] + rowbase * 32);
    uint4* dl = (uint4*)(g_Ast_lo[0] + rowbase * 32);
    const uint4* s4h = (const uint4*)sh[w];
    const uint4* s4l = (const uint4*)sl[w];
#pragma unroll
    for (int p = 0; p < 4; ++p) {
        dh[ln + 32 * p] = s4h[ln + 32 * p];
        dl[ln + 32 * p] = s4l[ln + 32 * p];
    }
}

// ---------------------------------------------------------------------------
// Persistent 17-layer chained GEMM. Grid (8,16) = 128 CTAs = one wave.
// - K-rotation: CTA (mi,ni) walks stages k=(j+ni*8)&63, so its first consumed
//   A-chunks at a layer boundary are the ones ITSELF just produced.
// - Weight conversion for matrix l+2 runs on the epilogue warps AFTER the
//   bar-1 TMEM handoff and BEFORE the done-wait, i.e. fully overlapped with
//   layer l's MMA mainloop (R9 had it before bar 1, which stalled the MMA).
// Warps 0-7: epilogue + W-convert. Warp 8: bulk producer. Warp 9: MMA.
// ---------------------------------------------------------------------------
#define BM 256
#define BN 256
#define NSTAGE 3
#define TILE_B 16384
#define STAGE_B (4 * TILE_B)  // 64KB
#define K_ITERS KSTAGES       // 64
#define EPI_SMEM 32768        // 8 warps x 4KB staging
#define MMA_IDESC 0x8400490u  // F32 acc, BF16 a/b, M=128, N=256

__global__ __launch_bounds__(320, 1)
void qgemm_persistent(float* __restrict__ outF,
                      const float* __restrict__ weights,
                      const float* __restrict__ meas) {
#if HAS_TCGEN05
    extern __shared__ __align__(1024) char smem_dyn[];
    __shared__ __align__(8) unsigned long long s_bars[7];
    __shared__ uint32_t s_tmem;

    const int tid = threadIdx.x;
    const int wid = tid >> 5;
    const int lid = tid & 31;

    const uint32_t raw = smem_u32(smem_dyn);
    const uint32_t smem_base = (raw + 1023u) & ~1023u;
    char* smem_g = smem_dyn + (smem_base - raw);

    uint32_t bar_full[3], bar_empty[3], bar_done;
#pragma unroll
    for (int i = 0; i < 3; ++i) {
        bar_full[i]  = smem_u32(&s_bars[i]);
        bar_empty[i] = smem_u32(&s_bars[3 + i]);
    }
    bar_done = smem_u32(&s_bars[6]);

    if (tid == 0) {
#pragma unroll
        for (int i = 0; i < 3; ++i) {
            MBARRIER_INIT(bar_full[i], 1);
            MBARRIER_INIT(bar_empty[i], 1);
        }
        MBARRIER_INIT(bar_done, 1);
    }
    if (wid == 8) TCGEN05_ALLOC(smem_u32(&s_tmem), 512);
    __syncthreads();
    const uint32_t tmem_d = s_tmem;

    const int mi = blockIdx.y;
    const int ni = blockIdx.x;
    const int blockN = ni * BN;
    const int blockM = mi * BM;
    const int rot = ni * 8;
    const size_t MATB = (size_t)KSTAGES * QD * 64;

    if (wid == 8) {
        // ---- producer warp (rotated stage order) ------------------------
        int s = 0, w = 0;
        for (int l = 0; l < NMAT; ++l) {
            // wait for this layer's weights to be converted (steady state:
            // converted two layers ago -> instant)
            if (l >= 2) {
                const int* wf = &g_wflags[l][ni];
                int v;
                do {
                    asm volatile("ld.acquire.gpu.global.b32 %0, [%1];"
                                 : "=r"(v) : "l"(wf) : "memory");
                } while (v < 16);
                asm volatile("fence.proxy.async;" ::: "memory");
            }
            unsigned long long ready = (l == 0) ? ~0ull : 0ull;
            for (int j = 0; j < K_ITERS; ++j) {
                const int k = (j + rot) & 63;
                if (l * K_ITERS + j >= NSTAGE)
                    MBARRIER_WAIT_PARITY(bar_empty[s], (w + 1) & 1);
                const uint32_t stage = smem_base + s * STAGE_B;
                const uint32_t ep = elect_one_pred();
                if (ep) MBARRIER_EXPECT_TX(bar_full[s], STAGE_B);
                const size_t boff = (size_t)l * MATB + ((size_t)k * QD + blockN) * 64;
                if (ep) {
                    bulk_cp(stage + 2 * TILE_B, (const char*)g_Wst_hi + boff, TILE_B, bar_full[s]);
                    bulk_cp(stage + 3 * TILE_B, (const char*)g_Wst_lo + boff, TILE_B, bar_full[s]);
                }
                // A: warp-cooperative poll of prev-layer chunk flags (j-space)
                while (!((ready >> j) & 1)) {
                    int idx = j + lid;
                    int v = 0;
                    if (idx < K_ITERS) {
                        const int ki = (idx + rot) & 63;
                        const int* f = &g_flags[l - 1][mi][ki >> 3][ki & 7];
                        asm volatile("ld.acquire.gpu.global.b32 %0, [%1];"
                                     : "=r"(v) : "l"(f) : "memory");
                    }
                    unsigned b = __ballot_sync(0xFFFFFFFFu, v >= 8);
                    ready |= ((unsigned long long)b) << j;
                }
                if (ep) {
                    asm volatile("fence.proxy.async;" ::: "memory");
                    const int pb = l & 1;
                    const size_t aoff = ((size_t)k * BATCH + blockM) * 64;
                    bulk_cp(stage,          (const char*)g_Ast_hi[pb] + aoff, TILE_B, bar_full[s]);
                    bulk_cp(stage + TILE_B, (const char*)g_Ast_lo[pb] + aoff, TILE_B, bar_full[s]);
                }
                if (++s == NSTAGE) { s = 0; ++w; }
            }
        }
    } else if (wid == 9) {
        // ---- MMA warp ---------------------------------------------------
        int s = 0, w = 0;
        for (int l = 0; l < NMAT; ++l) {
            asm volatile("bar.sync 1, 288;" ::: "memory");  // TMEM free handoff
            TCGEN05_FENCE_AFTER();
            for (int j = 0; j < K_ITERS; ++j) {
                MBARRIER_WAIT_PARITY(bar_full[s], w & 1);
                const uint32_t stage = smem_base + s * STAGE_B;
                if (elect_one_pred()) {
                    const uint64_t dBh = MAKE_DESC64(stage + 2 * TILE_B);
                    const uint64_t dBl = MAKE_DESC64(stage + 3 * TILE_B);
#pragma unroll
                    for (int h = 0; h < 2; ++h) {
                        const uint64_t dAh = MAKE_DESC64(stage + h * 8192);
                        const uint64_t dAl = MAKE_DESC64(stage + TILE_B + h * 8192);
                        const uint32_t d = tmem_d + h * 256;
#pragma unroll
                        for (int c = 0; c < 2; ++c) {
                            uint32_t en0 = (j == 0 && c == 0) ? 0u : 1u;
                            mma_f16_ss(d, dAh + 2 * c, dBh + 2 * c, MMA_IDESC, en0);
                            mma_f16_ss(d, dAh + 2 * c, dBl + 2 * c, MMA_IDESC, 1);
                            mma_f16_ss(d, dAl + 2 * c, dBh + 2 * c, MMA_IDESC, 1);
                        }
                    }
                    TCGEN05_COMMIT(bar_empty[s]);
                }
                if (++s == NSTAGE) { s = 0; ++w; }
            }
            if (elect_one_pred()) TCGEN05_COMMIT(bar_done);
        }
    } else {
        // ---- epilogue warps 0-7 (+ W conversion overlapped with MMA) ---
        const int half = wid >> 2;
        const int rbase = blockM + half * 128 + (wid & 3) * 32;
        const int row = rbase + lid;
        const int uperm = (lid >> 1) & 3;
        char* wsm = smem_g + NSTAGE * STAGE_B + wid * 4096;  // 2KB hi + 2KB lo
        for (int l = 0; l < NMAT; ++l) {
            // 1) release TMEM to the MMA warp FIRST
            asm volatile("bar.sync 1, 288;" ::: "memory");
            // 2) convert W[l+2] while layer l's mainloop runs
            if (l + 2 < NMAT) {
                const int m = l + 2;
                const float* src = (m < L_LAYERS) ? (weights + (size_t)m * QD * QD) : meas;
                const int sK = mi * 4 + (wid >> 1);   // stage handled by this warp
                const int rh = wid & 1;               // row half of the 256-slice
#pragma unroll 1
                for (int g = 0; g < 4; ++g) {
                    const int n0g = ni * 256 + rh * 128 + g * 32;
#pragma unroll 8
                    for (int jj = 0; jj < 32; ++jj) {
                        float x = src[(size_t)(sK * 32 + jj) * QD + n0g + lid];
                        __nv_bfloat16 hbf = __float2bfloat16(x);
                        __nv_bfloat16 lbf = __float2bfloat16(x - __bfloat162float(hbf));
                        int u = jj >> 3, e = jj & 7;
                        int pos = lid * 32 + ((u ^ uperm) << 3) + e;
                        ((__nv_bfloat16*)wsm)[pos] = hbf;
                        ((__nv_bfloat16*)(wsm + 2048))[pos] = lbf;
                    }
                    __syncwarp();
                    size_t rowbase = ((size_t)m * KSTAGES + sK) * QD + n0g;
                    uint4* dh = (uint4*)(g_Wst_hi + rowbase * 32);
                    uint4* dl = (uint4*)(g_Wst_lo + rowbase * 32);
                    const uint4* s4h = (const uint4*)wsm;
                    const uint4* s4l = (const uint4*)(wsm + 2048);
#pragma unroll
                    for (int p = 0; p < 4; ++p) {
                        dh[lid + 32 * p] = s4h[lid + 32 * p];
                        dl[lid + 32 * p] = s4l[lid + 32 * p];
                    }
                    __syncwarp();
                }
                asm volatile("bar.sync 3, 256;" ::: "memory");  // epi warps only
                if (wid == 0 && lid == 0) {
                    asm volatile("red.release.gpu.global.add.s32 [%0], 1;"
                                 :: "l"(&g_wflags[m][ni]) : "memory");
                }
            }
            // 3) wait for this layer's MMAs, then drain TMEM
            MBARRIER_WAIT_PARITY(bar_done, l & 1);
            TCGEN05_FENCE_AFTER();
            const float* scaleNext = (l < L_LAYERS - 1) ? g_scales[l + 1] : nullptr;
            const int fpout = (l == NMAT - 1);
            const int wb = (l + 1) & 1;
            __nv_bfloat16* outHi = g_Ast_hi[wb];
            __nv_bfloat16* outLo = g_Ast_lo[wb];
#pragma unroll 1
            for (int ch = 0; ch < 8; ++ch) {
                uint32_t regs[32];
                TCGEN05_LD_32X32B_X32(regs, tmem_d + half * 256 + ch * 32);
                TCGEN05_WAIT_LD();
                const int c0 = blockN + ch * 32;
                if (fpout) {
                    float* dst = outF + (size_t)row * QD + c0;
#pragma unroll
                    for (int g = 0; g < 8; ++g)
                        *(float4*)(dst + g * 4) = make_float4(
                            __uint_as_float(regs[g * 4 + 0]), __uint_as_float(regs[g * 4 + 1]),
                            __uint_as_float(regs[g * 4 + 2]), __uint_as_float(regs[g * 4 + 3]));
                } else {
                    uint32_t hp[16], lp[16];
#pragma unroll
                    for (int q = 0; q < 16; ++q) {
                        float v0 = __uint_as_float(regs[2 * q]);
                        float v1 = __uint_as_float(regs[2 * q + 1]);
                        if (scaleNext) {
                            const float2 s2 = *(const float2*)(scaleNext + c0 + 2 * q);
                            v0 *= s2.x;
                            v1 *= s2.y;
                        }
                        uint32_t b0 = __float_as_uint(v0), b1 = __float_as_uint(v1);
                        float lo0 = v0 - __uint_as_float(b0 & 0xFFFF0000u);
                        float lo1 = v1 - __uint_as_float(b1 & 0xFFFF0000u);
                        uint32_t hh;
                        asm("prmt.b32 %0, %1, %2, 0x7632;" : "=r"(hh) : "r"(b0), "r"(b1));
                        hp[q] = hh;
                        uint32_t lpk;
                        asm("cvt.rn.bf16x2.f32 %0, %1, %2;" : "=r"(lpk) : "f"(lo1), "f"(lo0));
                        lp[q] = lpk;
                    }
                    // stage into smem (swizzled), then coalesced 2KB copy-out
#pragma unroll
                    for (int u = 0; u < 4; ++u) {
                        int up = (u ^ uperm) << 4;
                        *(uint4*)(wsm + lid * 64 + up) =
                            make_uint4(hp[4 * u], hp[4 * u + 1], hp[4 * u + 2], hp[4 * u + 3]);
                        *(uint4*)(wsm + 2048 + lid * 64 + up) =
                            make_uint4(lp[4 * u], lp[4 * u + 1], lp[4 * u + 2], lp[4 * u + 3]);
                    }
                    __syncwarp();
                    const int sK2 = c0 >> 5;
                    size_t rowbase = (size_t)sK2 * BATCH + rbase;
                    uint4* dh = (uint4*)(outHi + rowbase * 32);
                    uint4* dl = (uint4*)(outLo + rowbase * 32);
                    const uint4* s4h = (const uint4*)wsm;
                    const uint4* s4l = (const uint4*)(wsm + 2048);
#pragma unroll
                    for (int p = 0; p < 4; ++p) {
                        dh[lid + 32 * p] = s4h[lid + 32 * p];
                        dl[lid + 32 * p] = s4l[lid + 32 * p];
                    }
                    __syncwarp();
                    if (lid == 0) {
                        asm volatile("red.release.gpu.global.add.s32 [%0], 1;"
                                     :: "l"(&g_flags[l][mi][ni][ch]) : "memory");
                    }
                }
            }
            TCGEN05_FENCE_BEFORE();
        }
    }

    __syncthreads();
    if (wid == 8) {
        TCGEN05_RELINQUISH();
        TCGEN05_DEALLOC(tmem_d, 512);
    }
#endif  // HAS_TCGEN05
}

// ---------------------------------------------------------------------------
// Launch
// ---------------------------------------------------------------------------
extern "C" void kernel_launch(void* const* d_in, const int* in_sizes, int n_in,
                              void* d_out, int out_size) {
    const float* input_state = (const float*)d_in[0];
    const float* angles      = (const float*)d_in[1];
    const float* weights     = (const float*)d_in[2];
    const float* meas_basis  = (const float*)d_in[3];
    float* out = (float*)d_out;
    (void)in_sizes; (void)n_in; (void)out_size;

    const size_t dyn = NSTAGE * STAGE_B + EPI_SMEM + 1024;  // 225 KB
    cudaFuncSetAttribute(qgemm_persistent, cudaFuncAttributeMaxDynamicSharedMemorySize, dyn);

    prep_small_kernel<<<128, 256>>>(angles);
    // only matrices 0 and 1 up front; the rest convert inside the GEMM
    convert_weights_staged<<<dim3(KSTAGES, QD / 256, 2), 256>>>(weights, meas_basis);
    convert_input_staged<<<dim3(KSTAGES, BATCH / 256), 256>>>(input_state);

    dim3 grid(QD / BN, BATCH / BM);  // (8, 16) = 128 CTAs, one wave
    qgemm_persistent<<<grid, 320, dyn>>>(out, weights, meas_basis);
}

// round 11
// speedup vs baseline: 1.0989x; 1.0108x over previous
#include <cuda_runtime.h>
#include <cuda_bf16.h>
#include <cstdint>
#include <math.h>

#define L_LAYERS 16
#define QD 2048
#define BATCH 4096
#define NMAT 17  // 16 layers + measurement basis

#if defined(__CUDA_ARCH_FEAT_SM103_ALL) || defined(__CUDA_ARCH_FEAT_SM100_ALL) || \
    (defined(__CUDA_ARCH_SPECIFIC__) && (__CUDA_ARCH_SPECIFIC__ >= 1000))
#define HAS_TCGEN05 1
#else
#define HAS_TCGEN05 0
#endif

// ---------------------------------------------------------------------------
// Device scratch. Operands in K-staged, SW64-pre-swizzled layout:
//   [K/32 stages][rows][32 bf16]  -> per-stage CTA tile is contiguous, fetched
// with one cp.async.bulk, landing exactly in SW64 layout for the MMA.
// ---------------------------------------------------------------------------
#define KSTAGES (QD / 32)  // 64
__device__ __nv_bfloat16 g_Wst_hi[(size_t)NMAT * KSTAGES * QD * 32];
__device__ __nv_bfloat16 g_Wst_lo[(size_t)NMAT * KSTAGES * QD * 32];
__device__ __nv_bfloat16 g_Ast_hi[2][(size_t)KSTAGES * BATCH * 32];
__device__ __nv_bfloat16 g_Ast_lo[2][(size_t)KSTAGES * BATCH * 32];
__device__ float g_scales[L_LAYERS][QD];
// per (layer, M-group, N-cta, chunk) arrival counters (8 epilogue warps each)
__device__ int g_flags[NMAT][16][8][8];
// per (matrix, N-cta) weight-conversion counters (16 mi-CTAs each)
__device__ int g_wflags[NMAT][8];

// ---------------------------------------------------------------------------
// PTX helpers
// ---------------------------------------------------------------------------
__device__ __forceinline__ uint32_t smem_u32(const void* p) {
    uint32_t a;
    asm("{ .reg .u64 t; cvta.to.shared.u64 t, %1; cvt.u32.u64 %0, t; }"
        : "=r"(a) : "l"(p));
    return a;
}

__device__ __forceinline__ uint32_t elect_one_pred() {
    uint32_t pred;
    asm volatile(
        "{\n\t.reg .pred p;\n\telect.sync _|p, 0xFFFFFFFF;\n\t"
        "selp.b32 %0, 1, 0, p;\n\t}"
        : "=r"(pred));
    return pred;
}

#define MBARRIER_INIT(addr, count) \
    asm volatile("mbarrier.init.shared.b64 [%0], %1;" \
                 :: "r"((uint32_t)(addr)), "r"((uint32_t)(count)) : "memory")

#define MBARRIER_EXPECT_TX(addr, tx) \
    asm volatile("mbarrier.arrive.expect_tx.shared.b64 _, [%0], %1;" \
                 :: "r"((uint32_t)(addr)), "r"((uint32_t)(tx)) : "memory")

// Arrive on the SAME smem offset in cluster CTA rank 0 (the pair leader).
#define MBARRIER_ARRIVE_LEADER(local_addr) \
    asm volatile( \
        "{\n\t.reg .b32 r;\n\t" \
        "mapa.shared::cluster.u32 r, %0, 0;\n\t" \
        "mbarrier.arrive.shared::cluster.b64 _, [r];\n\t}" \
        :: "r"((uint32_t)(local_addr)) : "memory")

#define MBARRIER_WAIT_PARITY(mbar_smem_addr, phase_parity) do { \
    uint32_t _mbar = (uint32_t)(mbar_smem_addr); \
    uint32_t _parity = (uint32_t)(phase_parity); \
    uint32_t _done; \
    asm volatile( \
        "{\n\t.reg .pred p;\n\t" \
        "mbarrier.try_wait.parity.acquire.cta.shared::cta.b64 p, [%1], %2;\n\t" \
        "selp.b32 %0, 1, 0, p;\n\t}" \
        : "=r"(_done) : "r"(_mbar), "r"(_parity) : "memory"); \
    if (!_done) { \
        asm volatile( \
            "{\n\t.reg .pred P1;\n\t" \
            "WAIT_LOOP_%=:\n\t" \
            "mbarrier.try_wait.parity.acquire.cta.shared::cta.b64 P1, [%0], %1, 0x989680;\n\t" \
            "@P1 bra.uni WAIT_DONE_%=;\n\t" \
            "bra.uni WAIT_LOOP_%=;\n\t" \
            "WAIT_DONE_%=:\n\t}" \
            :: "r"(_mbar), "r"(_parity) : "memory"); \
    } \
} while (0)

#define CLUSTER_SYNC() do { \
    asm volatile("barrier.cluster.arrive.aligned;" ::: "memory"); \
    asm volatile("barrier.cluster.wait.aligned;" ::: "memory"); \
} while (0)

__device__ __forceinline__ void bulk_cp(uint32_t dst, const void* src,
                                        uint32_t bytes, uint32_t mbar) {
    asm volatile(
        "cp.async.bulk.shared::cta.global.mbarrier::complete_tx::bytes "
        "[%0], [%1], %2, [%3];"
        :: "r"(dst), "l"(src), "r"(bytes), "r"(mbar) : "memory");
}

#if HAS_TCGEN05
#define TCGEN05_ALLOC_CG2(smem_result_addr, nCols) \
    asm volatile("tcgen05.alloc.cta_group::2.sync.aligned.shared::cta.b32 [%0], %1;" \
                 :: "r"((uint32_t)(smem_result_addr)), "r"((uint32_t)(nCols)) : "memory")
#define TCGEN05_DEALLOC_CG2(tmem_addr, nCols) \
    asm volatile("tcgen05.dealloc.cta_group::2.sync.aligned.b32 %0, %1;" \
                 :: "r"(tmem_addr), "r"((uint32_t)(nCols)))
#define TCGEN05_RELINQUISH_CG2() \
    asm volatile("tcgen05.relinquish_alloc_permit.cta_group::2.sync.aligned;")
// Commit: on MMA completion, arrive the SAME smem-offset mbarrier in both CTAs.
#define TCGEN05_COMMIT_MC(mbar) \
    asm volatile("tcgen05.commit.cta_group::2.mbarrier::arrive::one.shared::cluster.multicast::cluster.b64 [%0], %1;" \
                 :: "r"((uint32_t)(mbar)), "h"((uint16_t)3) : "memory")
#define TCGEN05_FENCE_AFTER() \
    asm volatile("tcgen05.fence::after_thread_sync;" ::: "memory")
#define TCGEN05_FENCE_BEFORE() \
    asm volatile("tcgen05.fence::before_thread_sync;" ::: "memory")
#define TCGEN05_WAIT_LD() \
    asm volatile("tcgen05.wait::ld.sync.aligned;" ::: "memory")

#define TCGEN05_LD_32X32B_X32(r, tmem_addr) \
    asm volatile( \
        "tcgen05.ld.sync.aligned.32x32b.x32.b32 " \
        "{%0, %1, %2, %3, %4, %5, %6, %7, " \
        " %8, %9, %10, %11, %12, %13, %14, %15, " \
        " %16, %17, %18, %19, %20, %21, %22, %23, " \
        " %24, %25, %26, %27, %28, %29, %30, %31}, [%32];" \
        : "=r"((r)[0]),  "=r"((r)[1]),  "=r"((r)[2]),  "=r"((r)[3]), \
          "=r"((r)[4]),  "=r"((r)[5]),  "=r"((r)[6]),  "=r"((r)[7]), \
          "=r"((r)[8]),  "=r"((r)[9]),  "=r"((r)[10]), "=r"((r)[11]), \
          "=r"((r)[12]), "=r"((r)[13]), "=r"((r)[14]), "=r"((r)[15]), \
          "=r"((r)[16]), "=r"((r)[17]), "=r"((r)[18]), "=r"((r)[19]), \
          "=r"((r)[20]), "=r"((r)[21]), "=r"((r)[22]), "=r"((r)[23]), \
          "=r"((r)[24]), "=r"((r)[25]), "=r"((r)[26]), "=r"((r)[27]), \
          "=r"((r)[28]), "=r"((r)[29]), "=r"((r)[30]), "=r"((r)[31]) \
        : "r"(tmem_addr))

// cg2 SS bf16 MMA: M=256 across the pair (HW reads 128 A-rows and 128 B-rows
// from EACH CTA's smem at the same descriptor offsets).
__device__ __forceinline__ void mma_f16_ss_cg2(uint32_t d, uint64_t da, uint64_t db,
                                               uint32_t idesc, uint32_t en) {
    asm volatile(
        "{\n\t.reg .pred p;\n\tsetp.ne.u32 p, %4, 0;\n\t"
        "tcgen05.mma.cta_group::2.kind::f16 [%0], %1, %2, %3, "
        "{%5,%5,%5,%5,%5,%5,%5,%5}, p;\n\t}"
        :: "r"(d), "l"(da), "l"(db), "r"(idesc), "r"(en), "r"(0u) : "memory");
}
#endif  // HAS_TCGEN05

// SW64 smem matrix descriptor: layout=4 (SW64), version=1, SBO=32, LBO=1.
static constexpr uint64_t DESC_SW64_BASE =
    (uint64_t(4) << 61) | (uint64_t(1) << 46) | (uint64_t(32) << 32) | (uint64_t(1) << 16);
#define MAKE_DESC64(a) (DESC_SW64_BASE | ((uint64_t)((a) >> 4) & 0x3FFF))

// ---------------------------------------------------------------------------
// Prep kernels (staged layout, SW64 swizzle pre-applied: unit u ^= (row>>1)&3)
// ---------------------------------------------------------------------------
__global__ void prep_small_kernel(const float* __restrict__ angles) {
    int idx = blockIdx.x * blockDim.x + threadIdx.x;
    if (idx < NMAT * 16 * 8 * 8) ((int*)g_flags)[idx] = 0;
    if (idx < NMAT * 8) ((int*)g_wflags)[idx] = 0;
    if (idx < L_LAYERS * QD) {
        const float* a = angles + idx * 3;
        (&g_scales[0][0])[idx] = cosf(0.5f * a[0]) * cosf(0.5f * a[1]) * cosf(0.5f * a[2]);
    }
}

// Pre-convert only matrices 0..1; the rest convert inside the persistent kernel.
__global__ void convert_weights_staged(const float* __restrict__ weights,
                                       const float* __restrict__ meas) {
    __shared__ __nv_bfloat16 sh[8][1024];
    __shared__ __nv_bfloat16 sl[8][1024];
    const int m = blockIdx.z;
    const float* src = (m < L_LAYERS) ? (weights + (size_t)m * QD * QD) : meas;
    const int sK = blockIdx.x;
    const int w = threadIdx.x >> 5, ln = threadIdx.x & 31;
    const int n0 = (blockIdx.y * 8 + w) * 32;
    const int uperm = (ln >> 1) & 3;
#pragma unroll 8
    for (int j = 0; j < 32; ++j) {
        float x = src[(size_t)(sK * 32 + j) * QD + n0 + ln];
        __nv_bfloat16 h = __float2bfloat16(x);
        __nv_bfloat16 l = __float2bfloat16(x - __bfloat162float(h));
        int u = j >> 3, e = j & 7;
        int pos = ln * 32 + ((u ^ uperm) << 3) + e;
        sh[w][pos] = h;
        sl[w][pos] = l;
    }
    __syncwarp();
    size_t rowbase = ((size_t)m * KSTAGES + sK) * QD + n0;
    uint4* dh = (uint4*)(g_Wst_hi + rowbase * 32);
    uint4* dl = (uint4*)(g_Wst_lo + rowbase * 32);
    const uint4* s4h = (const uint4*)sh[w];
    const uint4* s4l = (const uint4*)sl[w];
#pragma unroll
    for (int p = 0; p < 4; ++p) {
        dh[ln + 32 * p] = s4h[ln + 32 * p];
        dl[ln + 32 * p] = s4l[ln + 32 * p];
    }
}

__global__ void convert_input_staged(const float* __restrict__ in) {
    __shared__ __nv_bfloat16 sh[8][1024];
    __shared__ __nv_bfloat16 sl[8][1024];
    const int sK = blockIdx.x;
    const int w = threadIdx.x >> 5, ln = threadIdx.x & 31;
    const int r0 = (blockIdx.y * 8 + w) * 32;
    const float sc = g_scales[0][sK * 32 + ln];
    const int u = ln >> 3, e = ln & 7;
#pragma unroll 8
    for (int j = 0; j < 32; ++j) {
        float x = in[(size_t)(r0 + j) * QD + sK * 32 + ln] * sc;
        __nv_bfloat16 h = __float2bfloat16(x);
        __nv_bfloat16 l = __float2bfloat16(x - __bfloat162float(h));
        int pos = j * 32 + ((u ^ ((j >> 1) & 3)) << 3) + e;
        sh[w][pos] = h;
        sl[w][pos] = l;
    }
    __syncwarp();
    size_t rowbase = (size_t)sK * BATCH + r0;
    uint4* dh = (uint4*)(g_Ast_hi[0] + rowbase * 32);
    uint4* dl = (uint4*)(g_Ast_lo[0] + rowbase * 32);
    const uint4* s4h = (const uint4*)sh[w];
    const uint4* s4l = (const uint4*)sl[w];
#pragma unroll
    for (int p = 0; p < 4; ++p) {
        dh[ln + 32 * p] = s4h[ln + 32 * p];
        dl[ln + 32 * p] = s4l[ln + 32 * p];
    }
}

// ---------------------------------------------------------------------------
// Persistent 17-layer chained GEMM, cta_group::2 pairs.
// Grid (16 mi, 8 ni) = 128 CTAs = one wave; cluster (2,1,1) pairs (2t,2t+1)
// along mi with the same ni. The pair computes M=512xN=256 via two cg2 M=256
// sub-tiles; each CTA stages its own 256 A rows and its N-half of B (128
// rows) -> per-CTA smem reads/dispatch drop 12KB->8KB, B L2 traffic halves.
// Each CTA's TMEM holds exactly its own 256 rows (cols 0-255 = rows +0..127,
// cols 256-511 = rows +128..255) so the epilogue is unchanged.
// Warps 0-7: epilogue + W-convert. Warp 8: bulk producer.
// Warp 9: MMA issuer (leader) / relay (follower: forwards full-stage and
// tmem-free events to the leader via mapa mbarrier arrives).
// ---------------------------------------------------------------------------
#define NSTAGE 4
#define A_TILE 16384          // 256 rows x 64B (hi or lo)
#define B_TILE 8192           // 128 rows x 64B (hi or lo)
#define STAGE_B (2 * A_TILE + 2 * B_TILE)  // 48KB
#define OFF_ALO A_TILE
#define OFF_BHI (2 * A_TILE)
#define OFF_BLO (2 * A_TILE + B_TILE)
#define K_ITERS KSTAGES       // 64
#define EPI_SMEM 32768        // 8 warps x 4KB staging
#define IDESC_CG2 0x10400490u // F32 acc, BF16 a/b, M=256, N=256

__global__ __launch_bounds__(320, 1) __cluster_dims__(2, 1, 1)
void qgemm_persistent(float* __restrict__ outF,
                      const float* __restrict__ weights,
                      const float* __restrict__ meas) {
#if HAS_TCGEN05
    extern __shared__ __align__(1024) char smem_dyn[];
    // full[4] empty[4] peer_full[4] done tmem_free
    __shared__ __align__(8) unsigned long long s_bars[14];
    __shared__ uint32_t s_tmem;

    const int tid = threadIdx.x;
    const int wid = tid >> 5;
    const int lid = tid & 31;

    const uint32_t raw = smem_u32(smem_dyn);
    const uint32_t smem_base = (raw + 1023u) & ~1023u;
    char* smem_g = smem_dyn + (smem_base - raw);

    uint32_t bar_full[4], bar_empty[4], bar_pfull[4], bar_done, bar_tfree;
#pragma unroll
    for (int i = 0; i < 4; ++i) {
        bar_full[i]  = smem_u32(&s_bars[i]);
        bar_empty[i] = smem_u32(&s_bars[4 + i]);
        bar_pfull[i] = smem_u32(&s_bars[8 + i]);
    }
    bar_done  = smem_u32(&s_bars[12]);
    bar_tfree = smem_u32(&s_bars[13]);

    if (tid == 0) {
#pragma unroll
        for (int i = 0; i < 4; ++i) {
            MBARRIER_INIT(bar_full[i], 1);
            MBARRIER_INIT(bar_empty[i], 1);
            MBARRIER_INIT(bar_pfull[i], 1);
        }
        MBARRIER_INIT(bar_done, 1);
        MBARRIER_INIT(bar_tfree, 1);
    }
    if (wid == 9) TCGEN05_ALLOC_CG2(smem_u32(&s_tmem), 512);
    __syncthreads();
    CLUSTER_SYNC();  // peer mbarriers must be initialized before any cluster arrive
    const uint32_t tmem_d = s_tmem;

    const int mi = blockIdx.x;        // 0..15, M-group of 256 rows
    const int ni = blockIdx.y;        // 0..7,  N-cta of 256 cols
    const int rank = mi & 1;          // cluster_ctarank (cluster along x)
    const int blockM = mi * 256;
    const int blockN = ni * 256;
    const int rot = ni * 8;
    const size_t MATB = (size_t)KSTAGES * QD * 64;

    if (wid == 8) {
        // ---- producer warp (rotated stage order) ------------------------
        int s = 0, w = 0;
        for (int l = 0; l < NMAT; ++l) {
            if (l >= 2) {  // in-kernel converted weights ready?
                const int* wf = &g_wflags[l][ni];
                int v;
                do {
                    asm volatile("ld.acquire.gpu.global.b32 %0, [%1];"
                                 : "=r"(v) : "l"(wf) : "memory");
                } while (v < 16);
                asm volatile("fence.proxy.async;" ::: "memory");
            }
            unsigned long long ready = (l == 0) ? ~0ull : 0ull;
            for (int j = 0; j < K_ITERS; ++j) {
                const int k = (j + rot) & 63;
                if (l * K_ITERS + j >= NSTAGE)
                    MBARRIER_WAIT_PARITY(bar_empty[s], (w + 1) & 1);
                const uint32_t stage = smem_base + s * STAGE_B;
                const uint32_t ep = elect_one_pred();
                if (ep) MBARRIER_EXPECT_TX(bar_full[s], STAGE_B);
                // B: this CTA's N-half (128 rows)
                const size_t boff =
                    (size_t)l * MATB + ((size_t)k * QD + blockN + rank * 128) * 64;
                if (ep) {
                    bulk_cp(stage + OFF_BHI, (const char*)g_Wst_hi + boff, B_TILE, bar_full[s]);
                    bulk_cp(stage + OFF_BLO, (const char*)g_Wst_lo + boff, B_TILE, bar_full[s]);
                }
                // A: warp-cooperative poll of prev-layer chunk flags (j-space)
                while (!((ready >> j) & 1)) {
                    int idx = j + lid;
                    int v = 0;
                    if (idx < K_ITERS) {
                        const int ki = (idx + rot) & 63;
                        const int* f = &g_flags[l - 1][mi][ki >> 3][ki & 7];
                        asm volatile("ld.acquire.gpu.global.b32 %0, [%1];"
                                     : "=r"(v) : "l"(f) : "memory");
                    }
                    unsigned b = __ballot_sync(0xFFFFFFFFu, v >= 8);
                    ready |= ((unsigned long long)b) << j;
                }
                if (ep) {
                    asm volatile("fence.proxy.async;" ::: "memory");
                    const int pb = l & 1;
                    const size_t aoff = ((size_t)k * BATCH + blockM) * 64;
                    bulk_cp(stage,           (const char*)g_Ast_hi[pb] + aoff, A_TILE, bar_full[s]);
                    bulk_cp(stage + OFF_ALO, (const char*)g_Ast_lo[pb] + aoff, A_TILE, bar_full[s]);
                }
                if (++s == NSTAGE) { s = 0; ++w; }
            }
        }
    } else if (wid == 9) {
        if (rank == 0) {
            // ---- leader MMA warp ---------------------------------------
            int s = 0, w = 0;
            for (int l = 0; l < NMAT; ++l) {
                asm volatile("bar.sync 1, 288;" ::: "memory");      // own TMEM free
                MBARRIER_WAIT_PARITY(bar_tfree, l & 1);             // peer TMEM free
                TCGEN05_FENCE_AFTER();
                for (int j = 0; j < K_ITERS; ++j) {
                    MBARRIER_WAIT_PARITY(bar_full[s], w & 1);       // own stage
                    MBARRIER_WAIT_PARITY(bar_pfull[s], w & 1);      // peer stage
                    const uint32_t stage = smem_base + s * STAGE_B;
                    if (elect_one_pred()) {
                        const uint64_t dBh = MAKE_DESC64(stage + OFF_BHI);
                        const uint64_t dBl = MAKE_DESC64(stage + OFF_BLO);
#pragma unroll
                        for (int t = 0; t < 2; ++t) {  // sub-tile (A row half)
                            const uint64_t dAh = MAKE_DESC64(stage + t * 8192);
                            const uint64_t dAl = MAKE_DESC64(stage + OFF_ALO + t * 8192);
                            const uint32_t d = tmem_d + t * 256;
#pragma unroll
                            for (int c = 0; c < 2; ++c) {
                                uint32_t en0 = (j == 0 && c == 0) ? 0u : 1u;
                                mma_f16_ss_cg2(d, dAh + 2 * c, dBh + 2 * c, IDESC_CG2, en0);
                                mma_f16_ss_cg2(d, dAh + 2 * c, dBl + 2 * c, IDESC_CG2, 1);
                                mma_f16_ss_cg2(d, dAl + 2 * c, dBh + 2 * c, IDESC_CG2, 1);
                            }
                        }
                        TCGEN05_COMMIT_MC(bar_empty[s]);  // releases BOTH CTAs' stage
                    }
                    if (++s == NSTAGE) { s = 0; ++w; }
                }
                if (elect_one_pred()) TCGEN05_COMMIT_MC(bar_done);  // both CTAs
            }
        } else {
            // ---- follower relay warp -----------------------------------
            int s = 0, w = 0;
            for (int l = 0; l < NMAT; ++l) {
                asm volatile("bar.sync 1, 288;" ::: "memory");  // own epi released TMEM
                if (elect_one_pred()) MBARRIER_ARRIVE_LEADER(bar_tfree);
                for (int j = 0; j < K_ITERS; ++j) {
                    MBARRIER_WAIT_PARITY(bar_full[s], w & 1);
                    if (elect_one_pred()) MBARRIER_ARRIVE_LEADER(bar_pfull[s]);
                    if (++s == NSTAGE) { s = 0; ++w; }
                }
            }
        }
    } else {
        // ---- epilogue warps 0-7 (+ W conversion overlapped with MMA) ---
        const int half = wid >> 2;
        const int rbase = blockM + half * 128 + (wid & 3) * 32;
        const int row = rbase + lid;
        const int uperm = (lid >> 1) & 3;
        char* wsm = smem_g + NSTAGE * STAGE_B + wid * 4096;  // 2KB hi + 2KB lo
        for (int l = 0; l < NMAT; ++l) {
            // 1) release TMEM to the MMA warp FIRST
            asm volatile("bar.sync 1, 288;" ::: "memory");
            // 2) convert W[l+2] while layer l's mainloop runs
            if (l + 2 < NMAT) {
                const int m = l + 2;
                const float* src = (m < L_LAYERS) ? (weights + (size_t)m * QD * QD) : meas;
                const int sK = mi * 4 + (wid >> 1);
                const int rh = wid & 1;
#pragma unroll 1
                for (int g = 0; g < 4; ++g) {
                    const int n0g = ni * 256 + rh * 128 + g * 32;
#pragma unroll 8
                    for (int jj = 0; jj < 32; ++jj) {
                        float x = src[(size_t)(sK * 32 + jj) * QD + n0g + lid];
                        __nv_bfloat16 hbf = __float2bfloat16(x);
                        __nv_bfloat16 lbf = __float2bfloat16(x - __bfloat162float(hbf));
                        int u = jj >> 3, e = jj & 7;
                        int pos = lid * 32 + ((u ^ uperm) << 3) + e;
                        ((__nv_bfloat16*)wsm)[pos] = hbf;
                        ((__nv_bfloat16*)(wsm + 2048))[pos] = lbf;
                    }
                    __syncwarp();
                    size_t rowbase = ((size_t)m * KSTAGES + sK) * QD + n0g;
                    uint4* dh = (uint4*)(g_Wst_hi + rowbase * 32);
                    uint4* dl = (uint4*)(g_Wst_lo + rowbase * 32);
                    const uint4* s4h = (const uint4*)wsm;
                    const uint4* s4l = (const uint4*)(wsm + 2048);
#pragma unroll
                    for (int p = 0; p < 4; ++p) {
                        dh[lid + 32 * p] = s4h[lid + 32 * p];
                        dl[lid + 32 * p] = s4l[lid + 32 * p];
                    }
                    __syncwarp();
                }
                asm volatile("bar.sync 3, 256;" ::: "memory");  // epi warps only
                if (wid == 0 && lid == 0) {
                    asm volatile("red.release.gpu.global.add.s32 [%0], 1;"
                                 :: "l"(&g_wflags[m][ni]) : "memory");
                }
            }
            // 3) wait for this layer's MMAs, then drain TMEM
            MBARRIER_WAIT_PARITY(bar_done, l & 1);
            TCGEN05_FENCE_AFTER();
            const float* scaleNext = (l < L_LAYERS - 1) ? g_scales[l + 1] : nullptr;
            const int fpout = (l == NMAT - 1);
            const int wb = (l + 1) & 1;
            __nv_bfloat16* outHi = g_Ast_hi[wb];
            __nv_bfloat16* outLo = g_Ast_lo[wb];
#pragma unroll 1
            for (int ch = 0; ch < 8; ++ch) {
                uint32_t regs[32];
                TCGEN05_LD_32X32B_X32(regs, tmem_d + half * 256 + ch * 32);
                TCGEN05_WAIT_LD();
                const int c0 = blockN + ch * 32;
                if (fpout) {
                    float* dst = outF + (size_t)row * QD + c0;
#pragma unroll
                    for (int g = 0; g < 8; ++g)
                        *(float4*)(dst + g * 4) = make_float4(
                            __uint_as_float(regs[g * 4 + 0]), __uint_as_float(regs[g * 4 + 1]),
                            __uint_as_float(regs[g * 4 + 2]), __uint_as_float(regs[g * 4 + 3]));
                } else {
                    uint32_t hp[16], lp[16];
#pragma unroll
                    for (int q = 0; q < 16; ++q) {
                        float v0 = __uint_as_float(regs[2 * q]);
                        float v1 = __uint_as_float(regs[2 * q + 1]);
                        if (scaleNext) {
                            const float2 s2 = *(const float2*)(scaleNext + c0 + 2 * q);
                            v0 *= s2.x;
                            v1 *= s2.y;
                        }
                        uint32_t b0 = __float_as_uint(v0), b1 = __float_as_uint(v1);
                        float lo0 = v0 - __uint_as_float(b0 & 0xFFFF0000u);
                        float lo1 = v1 - __uint_as_float(b1 & 0xFFFF0000u);
                        uint32_t hh;
                        asm("prmt.b32 %0, %1, %2, 0x7632;" : "=r"(hh) : "r"(b0), "r"(b1));
                        hp[q] = hh;
                        uint32_t lpk;
                        asm("cvt.rn.bf16x2.f32 %0, %1, %2;" : "=r"(lpk) : "f"(lo1), "f"(lo0));
                        lp[q] = lpk;
                    }
#pragma unroll
                    for (int u = 0; u < 4; ++u) {
                        int up = (u ^ uperm) << 4;
                        *(uint4*)(wsm + lid * 64 + up) =
                            make_uint4(hp[4 * u], hp[4 * u + 1], hp[4 * u + 2], hp[4 * u + 3]);
                        *(uint4*)(wsm + 2048 + lid * 64 + up) =
                            make_uint4(lp[4 * u], lp[4 * u + 1], lp[4 * u + 2], lp[4 * u + 3]);
                    }
                    __syncwarp();
                    const int sK2 = c0 >> 5;
                    size_t rowbase = (size_t)sK2 * BATCH + rbase;
                    uint4* dh = (uint4*)(outHi + rowbase * 32);
                    uint4* dl = (uint4*)(outLo + rowbase * 32);
                    const uint4* s4h = (const uint4*)wsm;
                    const uint4* s4l = (const uint4*)(wsm + 2048);
#pragma unroll
                    for (int p = 0; p < 4; ++p) {
                        dh[lid + 32 * p] = s4h[lid + 32 * p];
                        dl[lid + 32 * p] = s4l[lid + 32 * p];
                    }
                    __syncwarp();
                    if (lid == 0) {
                        asm volatile("red.release.gpu.global.add.s32 [%0], 1;"
                                     :: "l"(&g_flags[l][mi][ni][ch]) : "memory");
                    }
                }
            }
            TCGEN05_FENCE_BEFORE();
        }
    }

    __syncthreads();
    CLUSTER_SYNC();  // both CTAs done with pair-shared smem/TMEM
    if (wid == 9) {
        TCGEN05_RELINQUISH_CG2();
        TCGEN05_DEALLOC_CG2(tmem_d, 512);
    }
    CLUSTER_SYNC();
#endif  // HAS_TCGEN05
}

// ---------------------------------------------------------------------------
// Launch
// ---------------------------------------------------------------------------
extern "C" void kernel_launch(void* const* d_in, const int* in_sizes, int n_in,
                              void* d_out, int out_size) {
    const float* input_state = (const float*)d_in[0];
    const float* angles      = (const float*)d_in[1];
    const float* weights     = (const float*)d_in[2];
    const float* meas_basis  = (const float*)d_in[3];
    float* out = (float*)d_out;
    (void)in_sizes; (void)n_in; (void)out_size;

    const size_t dyn = NSTAGE * STAGE_B + EPI_SMEM + 1024;  // 225 KB
    cudaFuncSetAttribute(qgemm_persistent, cudaFuncAttributeMaxDynamicSharedMemorySize, dyn);

    prep_small_kernel<<<128, 256>>>(angles);
    // only matrices 0 and 1 up front; the rest convert inside the GEMM
    convert_weights_staged<<<dim3(KSTAGES, QD / 256, 2), 256>>>(weights, meas_basis);
    convert_input_staged<<<dim3(KSTAGES, BATCH / 256), 256>>>(input_state);

    // grid: x = 16 M-groups (clusters of 2 along x), y = 8 N-ctas
    dim3 grid(16, 8);
    qgemm_persistent<<<grid, 320, dyn>>>(out, weights, meas_basis);
}

// round 15
// speedup vs baseline: 1.1047x; 1.0053x over previous
#include <cuda_runtime.h>
#include <cuda_bf16.h>
#include <cstdint>
#include <math.h>

#define L_LAYERS 16
#define QD 2048
#define BATCH 4096
#define NMAT 17  // 16 layers + measurement basis

#if defined(__CUDA_ARCH_FEAT_SM103_ALL) || defined(__CUDA_ARCH_FEAT_SM100_ALL) || \
    (defined(__CUDA_ARCH_SPECIFIC__) && (__CUDA_ARCH_SPECIFIC__ >= 1000))
#define HAS_TCGEN05 1
#else
#define HAS_TCGEN05 0
#endif

// ---------------------------------------------------------------------------
// Device scratch. Operands in K-staged, SW64-pre-swizzled layout:
//   [K/32 stages][rows][32 bf16]  -> per-stage CTA tile is contiguous, fetched
// with one cp.async.bulk, landing exactly in SW64 layout for the MMA.
// ---------------------------------------------------------------------------
#define KSTAGES (QD / 32)  // 64
__device__ __nv_bfloat16 g_Wst_hi[(size_t)NMAT * KSTAGES * QD * 32];
__device__ __nv_bfloat16 g_Wst_lo[(size_t)NMAT * KSTAGES * QD * 32];
__device__ __nv_bfloat16 g_Ast_hi[2][(size_t)KSTAGES * BATCH * 32];
__device__ __nv_bfloat16 g_Ast_lo[2][(size_t)KSTAGES * BATCH * 32];
__device__ float g_scales[L_LAYERS][QD];
// per (layer, M-group, N-cta, chunk) arrival counters (8 epilogue warps each)
__device__ int g_flags[NMAT][16][8][8];
// per (matrix, N-cta) weight-conversion counters (16 mi-CTAs each)
__device__ int g_wflags[NMAT][8];

// ---------------------------------------------------------------------------
// PTX helpers
// ---------------------------------------------------------------------------
__device__ __forceinline__ uint32_t smem_u32(const void* p) {
    uint32_t a;
    asm("{ .reg .u64 t; cvta.to.shared.u64 t, %1; cvt.u32.u64 %0, t; }"
        : "=r"(a) : "l"(p));
    return a;
}

__device__ __forceinline__ uint32_t elect_one_pred() {
    uint32_t pred;
    asm volatile(
        "{\n\t.reg .pred p;\n\telect.sync _|p, 0xFFFFFFFF;\n\t"
        "selp.b32 %0, 1, 0, p;\n\t}"
        : "=r"(pred));
    return pred;
}

#define MBARRIER_INIT(addr, count) \
    asm volatile("mbarrier.init.shared.b64 [%0], %1;" \
                 :: "r"((uint32_t)(addr)), "r"((uint32_t)(count)) : "memory")

#define MBARRIER_EXPECT_TX(addr, tx) \
    asm volatile("mbarrier.arrive.expect_tx.shared.b64 _, [%0], %1;" \
                 :: "r"((uint32_t)(addr)), "r"((uint32_t)(tx)) : "memory")

// Arrive on the SAME smem offset in cluster CTA rank 0 (the pair leader).
#define MBARRIER_ARRIVE_LEADER(local_addr) \
    asm volatile( \
        "{\n\t.reg .b32 r;\n\t" \
        "mapa.shared::cluster.u32 r, %0, 0;\n\t" \
        "mbarrier.arrive.shared::cluster.b64 _, [r];\n\t}" \
        :: "r"((uint32_t)(local_addr)) : "memory")

#define MBARRIER_WAIT_PARITY(mbar_smem_addr, phase_parity) do { \
    uint32_t _mbar = (uint32_t)(mbar_smem_addr); \
    uint32_t _parity = (uint32_t)(phase_parity); \
    uint32_t _done; \
    asm volatile( \
        "{\n\t.reg .pred p;\n\t" \
        "mbarrier.try_wait.parity.acquire.cta.shared::cta.b64 p, [%1], %2;\n\t" \
        "selp.b32 %0, 1, 0, p;\n\t}" \
        : "=r"(_done) : "r"(_mbar), "r"(_parity) : "memory"); \
    if (!_done) { \
        asm volatile( \
            "{\n\t.reg .pred P1;\n\t" \
            "WAIT_LOOP_%=:\n\t" \
            "mbarrier.try_wait.parity.acquire.cta.shared::cta.b64 P1, [%0], %1, 0x989680;\n\t" \
            "@P1 bra.uni WAIT_DONE_%=;\n\t" \
            "bra.uni WAIT_LOOP_%=;\n\t" \
            "WAIT_DONE_%=:\n\t}" \
            :: "r"(_mbar), "r"(_parity) : "memory"); \
    } \
} while (0)

#define CLUSTER_SYNC() do { \
    asm volatile("barrier.cluster.arrive.aligned;" ::: "memory"); \
    asm volatile("barrier.cluster.wait.aligned;" ::: "memory"); \
} while (0)

__device__ __forceinline__ void bulk_cp(uint32_t dst, const void* src,
                                        uint32_t bytes, uint32_t mbar) {
    asm volatile(
        "cp.async.bulk.shared::cta.global.mbarrier::complete_tx::bytes "
        "[%0], [%1], %2, [%3];"
        :: "r"(dst), "l"(src), "r"(bytes), "r"(mbar) : "memory");
}

#if HAS_TCGEN05
#define TCGEN05_ALLOC_CG2(smem_result_addr, nCols) \
    asm volatile("tcgen05.alloc.cta_group::2.sync.aligned.shared::cta.b32 [%0], %1;" \
                 :: "r"((uint32_t)(smem_result_addr)), "r"((uint32_t)(nCols)) : "memory")
#define TCGEN05_DEALLOC_CG2(tmem_addr, nCols) \
    asm volatile("tcgen05.dealloc.cta_group::2.sync.aligned.b32 %0, %1;" \
                 :: "r"(tmem_addr), "r"((uint32_t)(nCols)))
#define TCGEN05_RELINQUISH_CG2() \
    asm volatile("tcgen05.relinquish_alloc_permit.cta_group::2.sync.aligned;")
// Commit: on MMA completion, arrive the SAME smem-offset mbarrier in both CTAs.
#define TCGEN05_COMMIT_MC(mbar) \
    asm volatile("tcgen05.commit.cta_group::2.mbarrier::arrive::one.shared::cluster.multicast::cluster.b64 [%0], %1;" \
                 :: "r"((uint32_t)(mbar)), "h"((uint16_t)3) : "memory")
#define TCGEN05_FENCE_AFTER() \
    asm volatile("tcgen05.fence::after_thread_sync;" ::: "memory")
#define TCGEN05_FENCE_BEFORE() \
    asm volatile("tcgen05.fence::before_thread_sync;" ::: "memory")
#define TCGEN05_WAIT_LD() \
    asm volatile("tcgen05.wait::ld.sync.aligned;" ::: "memory")

#define TCGEN05_LD_32X32B_X32(r, tmem_addr) \
    asm volatile( \
        "tcgen05.ld.sync.aligned.32x32b.x32.b32 " \
        "{%0, %1, %2, %3, %4, %5, %6, %7, " \
        " %8, %9, %10, %11, %12, %13, %14, %15, " \
        " %16, %17, %18, %19, %20, %21, %22, %23, " \
        " %24, %25, %26, %27, %28, %29, %30, %31}, [%32];" \
        : "=r"((r)[0]),  "=r"((r)[1]),  "=r"((r)[2]),  "=r"((r)[3]), \
          "=r"((r)[4]),  "=r"((r)[5]),  "=r"((r)[6]),  "=r"((r)[7]), \
          "=r"((r)[8]),  "=r"((r)[9]),  "=r"((r)[10]), "=r"((r)[11]), \
          "=r"((r)[12]), "=r"((r)[13]), "=r"((r)[14]), "=r"((r)[15]), \
          "=r"((r)[16]), "=r"((r)[17]), "=r"((r)[18]), "=r"((r)[19]), \
          "=r"((r)[20]), "=r"((r)[21]), "=r"((r)[22]), "=r"((r)[23]), \
          "=r"((r)[24]), "=r"((r)[25]), "=r"((r)[26]), "=r"((r)[27]), \
          "=r"((r)[28]), "=r"((r)[29]), "=r"((r)[30]), "=r"((r)[31]) \
        : "r"(tmem_addr))

// cg2 SS bf16 MMA: M=256 across the pair (HW reads 128 A-rows and 128 B-rows
// from EACH CTA's smem at the same descriptor offsets).
__device__ __forceinline__ void mma_f16_ss_cg2(uint32_t d, uint64_t da, uint64_t db,
                                               uint32_t idesc, uint32_t en) {
    asm volatile(
        "{\n\t.reg .pred p;\n\tsetp.ne.u32 p, %4, 0;\n\t"
        "tcgen05.mma.cta_group::2.kind::f16 [%0], %1, %2, %3, "
        "{%5,%5,%5,%5,%5,%5,%5,%5}, p;\n\t}"
        :: "r"(d), "l"(da), "l"(db), "r"(idesc), "r"(en), "r"(0u) : "memory");
}
#endif  // HAS_TCGEN05

// SW64 smem matrix descriptor: layout=4 (SW64), version=1, SBO=32, LBO=1.
static constexpr uint64_t DESC_SW64_BASE =
    (uint64_t(4) << 61) | (uint64_t(1) << 46) | (uint64_t(32) << 32) | (uint64_t(1) << 16);
#define MAKE_DESC64(a) (DESC_SW64_BASE | ((uint64_t)((a) >> 4) & 0x3FFF))

// ---------------------------------------------------------------------------
// Prep kernels (staged layout, SW64 swizzle pre-applied: unit u ^= (row>>1)&3)
// ---------------------------------------------------------------------------
__global__ void prep_small_kernel(const float* __restrict__ angles) {
    int idx = blockIdx.x * blockDim.x + threadIdx.x;
    if (idx < NMAT * 16 * 8 * 8) ((int*)g_flags)[idx] = 0;
    if (idx < NMAT * 8) ((int*)g_wflags)[idx] = 0;
    if (idx < L_LAYERS * QD) {
        const float* a = angles + idx * 3;
        (&g_scales[0][0])[idx] = cosf(0.5f * a[0]) * cosf(0.5f * a[1]) * cosf(0.5f * a[2]);
    }
}

// Pre-convert only matrices 0..1; the rest convert inside the persistent kernel.
__global__ void convert_weights_staged(const float* __restrict__ weights,
                                       const float* __restrict__ meas) {
    __shared__ __nv_bfloat16 sh[8][1024];
    __shared__ __nv_bfloat16 sl[8][1024];
    const int m = blockIdx.z;
    const float* src = (m < L_LAYERS) ? (weights + (size_t)m * QD * QD) : meas;
    const int sK = blockIdx.x;
    const int w = threadIdx.x >> 5, ln = threadIdx.x & 31;
    const int n0 = (blockIdx.y * 8 + w) * 32;
    const int uperm = (ln >> 1) & 3;
#pragma unroll 8
    for (int j = 0; j < 32; ++j) {
        float x = src[(size_t)(sK * 32 + j) * QD + n0 + ln];
        __nv_bfloat16 h = __float2bfloat16(x);
        __nv_bfloat16 l = __float2bfloat16(x - __bfloat162float(h));
        int u = j >> 3, e = j & 7;
        int pos = ln * 32 + ((u ^ uperm) << 3) + e;
        sh[w][pos] = h;
        sl[w][pos] = l;
    }
    __syncwarp();
    size_t rowbase = ((size_t)m * KSTAGES + sK) * QD + n0;
    uint4* dh = (uint4*)(g_Wst_hi + rowbase * 32);
    uint4* dl = (uint4*)(g_Wst_lo + rowbase * 32);
    const uint4* s4h = (const uint4*)sh[w];
    const uint4* s4l = (const uint4*)sl[w];
#pragma unroll
    for (int p = 0; p < 4; ++p) {
        dh[ln + 32 * p] = s4h[ln + 32 * p];
        dl[ln + 32 * p] = s4l[ln + 32 * p];
    }
}

__global__ void convert_input_staged(const float* __restrict__ in) {
    __shared__ __nv_bfloat16 sh[8][1024];
    __shared__ __nv_bfloat16 sl[8][1024];
    const int sK = blockIdx.x;
    const int w = threadIdx.x >> 5, ln = threadIdx.x & 31;
    const int r0 = (blockIdx.y * 8 + w) * 32;
    const float sc = g_scales[0][sK * 32 + ln];
    const int u = ln >> 3, e = ln & 7;
#pragma unroll 8
    for (int j = 0; j < 32; ++j) {
        float x = in[(size_t)(r0 + j) * QD + sK * 32 + ln] * sc;
        __nv_bfloat16 h = __float2bfloat16(x);
        __nv_bfloat16 l = __float2bfloat16(x - __bfloat162float(h));
        int pos = j * 32 + ((u ^ ((j >> 1) & 3)) << 3) + e;
        sh[w][pos] = h;
        sl[w][pos] = l;
    }
    __syncwarp();
    size_t rowbase = (size_t)sK * BATCH + r0;
    uint4* dh = (uint4*)(g_Ast_hi[0] + rowbase * 32);
    uint4* dl = (uint4*)(g_Ast_lo[0] + rowbase * 32);
    const uint4* s4h = (const uint4*)sh[w];
    const uint4* s4l = (const uint4*)sl[w];
#pragma unroll
    for (int p = 0; p < 4; ++p) {
        dh[ln + 32 * p] = s4h[ln + 32 * p];
        dl[ln + 32 * p] = s4l[ln + 32 * p];
    }
}

// ---------------------------------------------------------------------------
// Persistent 17-layer chained GEMM, cta_group::2 pairs (R11 structure).
// Grid (16 mi, 8 ni) = 128 CTAs = one wave; cluster (2,1,1) along mi.
// CHANGE vs R11: the 12 MMA dispatches per K-iter are INTERLEAVED across the
// two TMEM accumulators (d, d+256) so no two consecutive dispatches target
// the same accumulator — breaks same-D RAW serialization in the tensor pipe.
// Warps 0-7: epilogue + W-convert. Warp 8: bulk producer.
// Warp 9: MMA issuer (leader) / full-stage + tmem-free relay (follower).
// ---------------------------------------------------------------------------
#define NSTAGE 4
#define A_TILE 16384          // 256 rows x 64B (hi or lo)
#define B_TILE 8192           // 128 rows x 64B (hi or lo)
#define STAGE_B (2 * A_TILE + 2 * B_TILE)  // 48KB
#define OFF_ALO A_TILE
#define OFF_BHI (2 * A_TILE)
#define OFF_BLO (2 * A_TILE + B_TILE)
#define K_ITERS KSTAGES       // 64
#define EPI_SMEM 32768        // 8 warps x 4KB staging
#define IDESC_CG2 0x10400490u // F32 acc, BF16 a/b, M=256, N=256

__global__ __launch_bounds__(320, 1) __cluster_dims__(2, 1, 1)
void qgemm_persistent(float* __restrict__ outF,
                      const float* __restrict__ weights,
                      const float* __restrict__ meas) {
#if HAS_TCGEN05
    extern __shared__ __align__(1024) char smem_dyn[];
    // full[4] empty[4] peer_full[4] done tmem_free
    __shared__ __align__(8) unsigned long long s_bars[14];
    __shared__ uint32_t s_tmem;

    const int tid = threadIdx.x;
    const int wid = tid >> 5;
    const int lid = tid & 31;

    const uint32_t raw = smem_u32(smem_dyn);
    const uint32_t smem_base = (raw + 1023u) & ~1023u;
    char* smem_g = smem_dyn + (smem_base - raw);

    uint32_t bar_full[4], bar_empty[4], bar_pfull[4], bar_done, bar_tfree;
#pragma unroll
    for (int i = 0; i < 4; ++i) {
        bar_full[i]  = smem_u32(&s_bars[i]);
        bar_empty[i] = smem_u32(&s_bars[4 + i]);
        bar_pfull[i] = smem_u32(&s_bars[8 + i]);
    }
    bar_done  = smem_u32(&s_bars[12]);
    bar_tfree = smem_u32(&s_bars[13]);

    if (tid == 0) {
#pragma unroll
        for (int i = 0; i < 4; ++i) {
            MBARRIER_INIT(bar_full[i], 1);
            MBARRIER_INIT(bar_empty[i], 1);
            MBARRIER_INIT(bar_pfull[i], 1);
        }
        MBARRIER_INIT(bar_done, 1);
        MBARRIER_INIT(bar_tfree, 1);
    }
    if (wid == 9) TCGEN05_ALLOC_CG2(smem_u32(&s_tmem), 512);
    __syncthreads();
    CLUSTER_SYNC();  // peer mbarriers must be initialized before cluster traffic
    const uint32_t tmem_d = s_tmem;

    const int mi = blockIdx.x;        // 0..15, M-group of 256 rows
    const int ni = blockIdx.y;        // 0..7,  N-cta of 256 cols
    const int rank = mi & 1;          // cluster_ctarank (cluster along x)
    const int blockM = mi * 256;
    const int blockN = ni * 256;
    const int rot = ni * 8;
    const size_t MATB = (size_t)KSTAGES * QD * 64;

    if (wid == 8) {
        // ---- producer warp (rotated stage order) ------------------------
        int s = 0, w = 0;
        for (int l = 0; l < NMAT; ++l) {
            if (l >= 2) {  // in-kernel converted weights ready?
                const int* wf = &g_wflags[l][ni];
                int v;
                do {
                    asm volatile("ld.acquire.gpu.global.b32 %0, [%1];"
                                 : "=r"(v) : "l"(wf) : "memory");
                } while (v < 16);
                asm volatile("fence.proxy.async;" ::: "memory");
            }
            unsigned long long ready = (l == 0) ? ~0ull : 0ull;
            for (int j = 0; j < K_ITERS; ++j) {
                const int k = (j + rot) & 63;
                if (l * K_ITERS + j >= NSTAGE)
                    MBARRIER_WAIT_PARITY(bar_empty[s], (w + 1) & 1);
                const uint32_t stage = smem_base + s * STAGE_B;
                const uint32_t ep = elect_one_pred();
                if (ep) MBARRIER_EXPECT_TX(bar_full[s], STAGE_B);
                // B: this CTA's N-half (128 rows)
                const size_t boff =
                    (size_t)l * MATB + ((size_t)k * QD + blockN + rank * 128) * 64;
                if (ep) {
                    bulk_cp(stage + OFF_BHI, (const char*)g_Wst_hi + boff, B_TILE, bar_full[s]);
                    bulk_cp(stage + OFF_BLO, (const char*)g_Wst_lo + boff, B_TILE, bar_full[s]);
                }
                // A: warp-cooperative poll of prev-layer chunk flags (j-space)
                while (!((ready >> j) & 1)) {
                    int idx = j + lid;
                    int v = 0;
                    if (idx < K_ITERS) {
                        const int ki = (idx + rot) & 63;
                        const int* f = &g_flags[l - 1][mi][ki >> 3][ki & 7];
                        asm volatile("ld.acquire.gpu.global.b32 %0, [%1];"
                                     : "=r"(v) : "l"(f) : "memory");
                    }
                    unsigned b = __ballot_sync(0xFFFFFFFFu, v >= 8);
                    ready |= ((unsigned long long)b) << j;
                }
                if (ep) {
                    asm volatile("fence.proxy.async;" ::: "memory");
                    const int pb = l & 1;
                    const size_t aoff = ((size_t)k * BATCH + blockM) * 64;
                    bulk_cp(stage,           (const char*)g_Ast_hi[pb] + aoff, A_TILE, bar_full[s]);
                    bulk_cp(stage + OFF_ALO, (const char*)g_Ast_lo[pb] + aoff, A_TILE, bar_full[s]);
                }
                if (++s == NSTAGE) { s = 0; ++w; }
            }
        }
    } else if (wid == 9) {
        if (rank == 0) {
            // ---- leader MMA warp (interleaved accumulators) ------------
            int s = 0, w = 0;
            for (int l = 0; l < NMAT; ++l) {
                asm volatile("bar.sync 1, 288;" ::: "memory");      // own TMEM free
                MBARRIER_WAIT_PARITY(bar_tfree, l & 1);             // peer TMEM free
                TCGEN05_FENCE_AFTER();
                for (int j = 0; j < K_ITERS; ++j) {
                    MBARRIER_WAIT_PARITY(bar_full[s], w & 1);       // own stage
                    MBARRIER_WAIT_PARITY(bar_pfull[s], w & 1);      // peer stage
                    const uint32_t stage = smem_base + s * STAGE_B;
                    if (elect_one_pred()) {
                        const uint64_t dBh = MAKE_DESC64(stage + OFF_BHI);
                        const uint64_t dBl = MAKE_DESC64(stage + OFF_BLO);
                        const uint64_t dAh0 = MAKE_DESC64(stage);
                        const uint64_t dAl0 = MAKE_DESC64(stage + OFF_ALO);
                        const uint64_t dAh1 = MAKE_DESC64(stage + 8192);
                        const uint64_t dAl1 = MAKE_DESC64(stage + OFF_ALO + 8192);
                        const uint32_t d0 = tmem_d, d1 = tmem_d + 256;
#pragma unroll
                        for (int c = 0; c < 2; ++c) {
                            const uint32_t en0 = (j == 0 && c == 0) ? 0u : 1u;
                            const uint64_t o = 2 * c;
                            // interleave: no two consecutive dispatches share D
                            mma_f16_ss_cg2(d0, dAh0 + o, dBh + o, IDESC_CG2, en0);
                            mma_f16_ss_cg2(d1, dAh1 + o, dBh + o, IDESC_CG2, en0);
                            mma_f16_ss_cg2(d0, dAh0 + o, dBl + o, IDESC_CG2, 1);
                            mma_f16_ss_cg2(d1, dAh1 + o, dBl + o, IDESC_CG2, 1);
                            mma_f16_ss_cg2(d0, dAl0 + o, dBh + o, IDESC_CG2, 1);
                            mma_f16_ss_cg2(d1, dAl1 + o, dBh + o, IDESC_CG2, 1);
                        }
                        TCGEN05_COMMIT_MC(bar_empty[s]);  // releases BOTH CTAs' stage
                    }
                    if (++s == NSTAGE) { s = 0; ++w; }
                }
                if (elect_one_pred()) TCGEN05_COMMIT_MC(bar_done);  // both CTAs
            }
        } else {
            // ---- follower relay warp -----------------------------------
            int s = 0, w = 0;
            for (int l = 0; l < NMAT; ++l) {
                asm volatile("bar.sync 1, 288;" ::: "memory");  // own epi freed TMEM
                if (elect_one_pred()) MBARRIER_ARRIVE_LEADER(bar_tfree);
                for (int j = 0; j < K_ITERS; ++j) {
                    MBARRIER_WAIT_PARITY(bar_full[s], w & 1);
                    if (elect_one_pred()) MBARRIER_ARRIVE_LEADER(bar_pfull[s]);
                    if (++s == NSTAGE) { s = 0; ++w; }
                }
            }
        }
    } else {
        // ---- epilogue warps 0-7 (+ W conversion overlapped with MMA) ---
        const int half = wid >> 2;
        const int rbase = blockM + half * 128 + (wid & 3) * 32;
        const int row = rbase + lid;
        const int uperm = (lid >> 1) & 3;
        char* wsm = smem_g + NSTAGE * STAGE_B + wid * 4096;  // 2KB hi + 2KB lo
        for (int l = 0; l < NMAT; ++l) {
            // 1) release TMEM to the MMA warp FIRST
            asm volatile("bar.sync 1, 288;" ::: "memory");
            // 2) convert W[l+2] while layer l's mainloop runs
            if (l + 2 < NMAT) {
                const int m = l + 2;
                const float* src = (m < L_LAYERS) ? (weights + (size_t)m * QD * QD) : meas;
                const int sK = mi * 4 + (wid >> 1);
                const int rh = wid & 1;
#pragma unroll 1
                for (int g = 0; g < 4; ++g) {
                    const int n0g = ni * 256 + rh * 128 + g * 32;
#pragma unroll 8
                    for (int jj = 0; jj < 32; ++jj) {
                        float x = src[(size_t)(sK * 32 + jj) * QD + n0g + lid];
                        __nv_bfloat16 hbf = __float2bfloat16(x);
                        __nv_bfloat16 lbf = __float2bfloat16(x - __bfloat162float(hbf));
                        int u = jj >> 3, e = jj & 7;
                        int pos = lid * 32 + ((u ^ uperm) << 3) + e;
                        ((__nv_bfloat16*)wsm)[pos] = hbf;
                        ((__nv_bfloat16*)(wsm + 2048))[pos] = lbf;
                    }
                    __syncwarp();
                    size_t rowbase = ((size_t)m * KSTAGES + sK) * QD + n0g;
                    uint4* dh = (uint4*)(g_Wst_hi + rowbase * 32);
                    uint4* dl = (uint4*)(g_Wst_lo + rowbase * 32);
                    const uint4* s4h = (const uint4*)wsm;
                    const uint4* s4l = (const uint4*)(wsm + 2048);
#pragma unroll
                    for (int p = 0; p < 4; ++p) {
                        dh[lid + 32 * p] = s4h[lid + 32 * p];
                        dl[lid + 32 * p] = s4l[lid + 32 * p];
                    }
                    __syncwarp();
                }
                asm volatile("bar.sync 3, 256;" ::: "memory");  // epi warps only
                if (wid == 0 && lid == 0) {
                    asm volatile("red.release.gpu.global.add.s32 [%0], 1;"
                                 :: "l"(&g_wflags[m][ni]) : "memory");
                }
            }
            // 3) wait for this layer's MMAs, then drain TMEM
            MBARRIER_WAIT_PARITY(bar_done, l & 1);
            TCGEN05_FENCE_AFTER();
            const float* scaleNext = (l < L_LAYERS - 1) ? g_scales[l + 1] : nullptr;
            const int fpout = (l == NMAT - 1);
            const int wb = (l + 1) & 1;
            __nv_bfloat16* outHi = g_Ast_hi[wb];
            __nv_bfloat16* outLo = g_Ast_lo[wb];
#pragma unroll 1
            for (int ch = 0; ch < 8; ++ch) {
                uint32_t regs[32];
                TCGEN05_LD_32X32B_X32(regs, tmem_d + half * 256 + ch * 32);
                TCGEN05_WAIT_LD();
                const int c0 = blockN + ch * 32;
                if (fpout) {
                    float* dst = outF + (size_t)row * QD + c0;
#pragma unroll
                    for (int g = 0; g < 8; ++g)
                        *(float4*)(dst + g * 4) = make_float4(
                            __uint_as_float(regs[g * 4 + 0]), __uint_as_float(regs[g * 4 + 1]),
                            __uint_as_float(regs[g * 4 + 2]), __uint_as_float(regs[g * 4 + 3]));
                } else {
                    uint32_t hp[16], lp[16];
#pragma unroll
                    for (int q = 0; q < 16; ++q) {
                        float v0 = __uint_as_float(regs[2 * q]);
                        float v1 = __uint_as_float(regs[2 * q + 1]);
                        if (scaleNext) {
                            const float2 s2 = *(const float2*)(scaleNext + c0 + 2 * q);
                            v0 *= s2.x;
                            v1 *= s2.y;
                        }
                        uint32_t b0 = __float_as_uint(v0), b1 = __float_as_uint(v1);
                        float lo0 = v0 - __uint_as_float(b0 & 0xFFFF0000u);
                        float lo1 = v1 - __uint_as_float(b1 & 0xFFFF0000u);
                        uint32_t hh;
                        asm("prmt.b32 %0, %1, %2, 0x7632;" : "=r"(hh) : "r"(b0), "r"(b1));
                        hp[q] = hh;
                        uint32_t lpk;
                        asm("cvt.rn.bf16x2.f32 %0, %1, %2;" : "=r"(lpk) : "f"(lo1), "f"(lo0));
                        lp[q] = lpk;
                    }
#pragma unroll
                    for (int u = 0; u < 4; ++u) {
                        int up = (u ^ uperm) << 4;
                        *(uint4*)(wsm + lid * 64 + up) =
                            make_uint4(hp[4 * u], hp[4 * u + 1], hp[4 * u + 2], hp[4 * u + 3]);
                        *(uint4*)(wsm + 2048 + lid * 64 + up) =
                            make_uint4(lp[4 * u], lp[4 * u + 1], lp[4 * u + 2], lp[4 * u + 3]);
                    }
                    __syncwarp();
                    const int sK2 = c0 >> 5;
                    size_t rowbase = (size_t)sK2 * BATCH + rbase;
                    uint4* dh = (uint4*)(outHi + rowbase * 32);
                    uint4* dl = (uint4*)(outLo + rowbase * 32);
                    const uint4* s4h = (const uint4*)wsm;
                    const uint4* s4l = (const uint4*)(wsm + 2048);
#pragma unroll
                    for (int p = 0; p < 4; ++p) {
                        dh[lid + 32 * p] = s4h[lid + 32 * p];
                        dl[lid + 32 * p] = s4l[lid + 32 * p];
                    }
                    __syncwarp();
                    if (lid == 0) {
                        asm volatile("red.release.gpu.global.add.s32 [%0], 1;"
                                     :: "l"(&g_flags[l][mi][ni][ch]) : "memory");
                    }
                }
            }
            TCGEN05_FENCE_BEFORE();
        }
    }

    __syncthreads();
    CLUSTER_SYNC();  // both CTAs done with pair-shared smem/TMEM
    if (wid == 9) {
        TCGEN05_RELINQUISH_CG2();
        TCGEN05_DEALLOC_CG2(tmem_d, 512);
    }
    CLUSTER_SYNC();
#endif  // HAS_TCGEN05
}

// ---------------------------------------------------------------------------
// Launch
// ---------------------------------------------------------------------------
extern "C" void kernel_launch(void* const* d_in, const int* in_sizes, int n_in,
                              void* d_out, int out_size) {
    const float* input_state = (const float*)d_in[0];
    const float* angles      = (const float*)d_in[1];
    const float* weights     = (const float*)d_in[2];
    const float* meas_basis  = (const float*)d_in[3];
    float* out = (float*)d_out;
    (void)in_sizes; (void)n_in; (void)out_size;

    const size_t dyn = NSTAGE * STAGE_B + EPI_SMEM + 1024;  // 225 KB
    cudaFuncSetAttribute(qgemm_persistent, cudaFuncAttributeMaxDynamicSharedMemorySize, dyn);

    prep_small_kernel<<<128, 256>>>(angles);
    // only matrices 0 and 1 up front; the rest convert inside the GEMM
    convert_weights_staged<<<dim3(KSTAGES, QD / 256, 2), 256>>>(weights, meas_basis);
    convert_input_staged<<<dim3(KSTAGES, BATCH / 256), 256>>>(input_state);

    // grid: x = 16 M-groups (clusters of 2 along x), y = 8 N-ctas
    dim3 grid(16, 8);
    qgemm_persistent<<<grid, 320, dyn>>>(out, weights, meas_basis);
}